// round 1
// baseline (speedup 1.0000x reference)
#include <cuda_runtime.h>
#include <cstdint>
#include <math.h>

#define B_ 8
#define C_ 64
#define H_ 256
#define W_ 256
#define P_ (H_*W_)
#define K_ 2048
#define NFG 1024
#define NHARD 768
#define NRAND 256
#define RADIUS_ 10
#define INV_T (1.0f/0.07f)

// -------- scratch (static __device__, no allocations) --------
__device__ unsigned char g_rowdil[B_*P_];
__device__ unsigned char g_cat[B_*P_];     // bit0 = fg, bit1 = dilated
__device__ int   g_idx[B_*K_];
__device__ int   g_ys [B_*K_];
__device__ float g_fsn[B_*K_*C_];
__device__ float g_loss_sum[B_];
__device__ int   g_valid[B_];

// -------- Threefry-2x32 (matches JAX threefry2x32 exactly) --------
__host__ __device__ inline void tf2x32(uint32_t k0, uint32_t k1,
                                       uint32_t x0, uint32_t x1,
                                       uint32_t& o0, uint32_t& o1) {
    uint32_t ks2 = k0 ^ k1 ^ 0x1BD11BDAu;
    x0 += k0; x1 += k1;
#define RR(r) { x0 += x1; x1 = (x1 << r) | (x1 >> (32 - r)); x1 ^= x0; }
    RR(13) RR(15) RR(26) RR(6)  x0 += k1;  x1 += ks2 + 1u;
    RR(17) RR(29) RR(16) RR(24) x0 += ks2; x1 += k0  + 2u;
    RR(13) RR(15) RR(26) RR(6)  x0 += k0;  x1 += k1  + 3u;
    RR(17) RR(29) RR(16) RR(24) x0 += k1;  x1 += ks2 + 4u;
    RR(13) RR(15) RR(26) RR(6)  x0 += ks2; x1 += k0  + 5u;
#undef RR
    o0 = x0; o1 = x1;
}

// -------- init --------
__global__ void init_kernel() {
    int t = threadIdx.x;
    if (t < B_) { g_loss_sum[t] = 0.0f; g_valid[t] = 0; }
}

// -------- masks: separable 21x21 max-pool dilation --------
__global__ void rowdil_kernel(const int* __restrict__ labels) {
    int b = blockIdx.y, i = blockIdx.x, j = threadIdx.x;
    __shared__ unsigned char row[W_];
    int p = i * W_ + j;
    int fg = (labels[b * P_ + p] == 1);
    row[j] = (unsigned char)fg;
    __syncthreads();
    int lo = j - RADIUS_; if (lo < 0) lo = 0;
    int hi = j + RADIUS_; if (hi > W_ - 1) hi = W_ - 1;
    unsigned char od = 0;
    for (int jj = lo; jj <= hi; ++jj) od |= row[jj];
    g_rowdil[b * P_ + p] = od;
    g_cat[b * P_ + p] = (unsigned char)fg;
}

__global__ void coldil_kernel() {
    int b = blockIdx.y, i = blockIdx.x, j = threadIdx.x;
    int lo = i - RADIUS_; if (lo < 0) lo = 0;
    int hi = i + RADIUS_; if (hi > H_ - 1) hi = H_ - 1;
    unsigned char d = 0;
    for (int ii = lo; ii <= hi; ++ii) d |= g_rowdil[b * P_ + ii * W_ + j];
    int p = i * W_ + j;
    if (d) g_cat[b * P_ + p] |= 2;
}

// -------- selection: top-n uniforms per (image,pick), histogram radix-select --------
struct KeyArg { uint32_t k[B_][3][2]; };

__global__ void __launch_bounds__(1024) select_kernel(KeyArg ka) {
    int b = blockIdx.x / 3, pick = blockIdx.x % 3;
    int n    = (pick == 0) ? NFG : (pick == 1) ? NHARD : NRAND;
    int base = b * K_ + ((pick == 0) ? 0 : (pick == 1) ? NFG : (NFG + NHARD));
    uint32_t k0 = ka.k[b][pick][0], k1 = ka.k[b][pick][1];
    int t = threadIdx.x;

    __shared__ unsigned int hist[2048];
    __shared__ unsigned long long cand[4096];
    __shared__ int s_bstar, s_above, s_total, s_ccnt, s_ocnt;

    for (int q = t; q < 2048; q += 1024) hist[q] = 0u;
    if (t == 0) s_ccnt = 0;
    __syncthreads();

    const unsigned char* cat = g_cat + b * P_;
    // pick0: fg ; pick1: dil & !fg ; pick2: !fg & !dil
    auto inmask = [&] (unsigned char c) -> bool {
        unsigned char m = c & 3;
        return (pick == 0) ? (m & 1) : (pick == 1) ? (m == 2) : (m == 0);
    };

    // pass 1: histogram of 23-bit mantissa values
    for (int kk = 0; kk < 32; ++kk) {
        int j = kk * 1024 + t;
        uint32_t o0, o1;
        tf2x32(k0, k1, (uint32_t)j, (uint32_t)(j + 32768), o0, o1);
        if (inmask(cat[j]))         atomicAdd(&hist[o0 >> 21], 1u);
        if (inmask(cat[j + 32768])) atomicAdd(&hist[o1 >> 21], 1u);
    }
    __syncthreads();

    if (t == 0) {
        int cum = 0, bstar = -1, above = 0;
        for (int q = 2047; q >= 0; --q) {
            int h = (int)hist[q];
            if (bstar < 0 && cum + h >= n) { bstar = q; above = cum; }
            cum += h;
        }
        s_bstar = bstar; s_above = above; s_total = cum; s_ocnt = 0;
    }
    __syncthreads();

    if (s_total >= n) {
        int bstar = s_bstar;
        // pass 2: emit strictly-above-bin elements, collect boundary-bin candidates
        for (int kk = 0; kk < 32; ++kk) {
            int j = kk * 1024 + t;
            uint32_t o0, o1;
            tf2x32(k0, k1, (uint32_t)j, (uint32_t)(j + 32768), o0, o1);
            #pragma unroll
            for (int h = 0; h < 2; ++h) {
                int p = h ? (j + 32768) : j;
                uint32_t m = (h ? o1 : o0) >> 9;          // 23-bit value
                if (inmask(cat[p])) {
                    int bin = (int)(m >> 12);
                    if (bin > bstar) {
                        int slot = atomicAdd(&s_ocnt, 1);
                        g_idx[base + slot] = p;
                    } else if (bin == bstar) {
                        int c = atomicAdd(&s_ccnt, 1);
                        if (c < 4096)
                            // value desc, then index asc (top_k tie rule)
                            cand[c] = ((unsigned long long)m << 16)
                                      | (unsigned long long)(0xFFFFu - (uint32_t)p);
                    }
                }
            }
        }
        __syncthreads();
        int c = s_ccnt < 4096 ? s_ccnt : 4096;
        int r = n - s_above;
        for (int ci = t; ci < c; ci += 1024) {
            unsigned long long v = cand[ci];
            int rank = 0;
            for (int q = 0; q < c; ++q) rank += (cand[q] > v);
            if (rank < r) {
                int slot = atomicAdd(&s_ocnt, 1);
                g_idx[base + slot] = 0xFFFF - (int)(v & 0xFFFFull);
            }
        }
    } else {
        // degenerate pool (not hit for this input, kept for safety):
        // all masked, then lowest-index unmasked
        if (t == 0) {
            int cnt = 0;
            for (int p = 0; p < P_ && cnt < n; ++p) if ( inmask(cat[p])) g_idx[base + cnt++] = p;
            for (int p = 0; p < P_ && cnt < n; ++p) if (!inmask(cat[p])) g_idx[base + cnt++] = p;
        }
    }
}

// -------- gather + L2-normalize (one warp per sample) --------
__global__ void gather_kernel(const float* __restrict__ feats,
                              const int* __restrict__ labels) {
    int gw   = (blockIdx.x * blockDim.x + threadIdx.x) >> 5;
    int lane = threadIdx.x & 31;
    if (gw >= B_ * K_) return;
    int b = gw / K_;
    int p = g_idx[gw];
    const float* f = feats + (size_t)b * C_ * P_ + p;
    float v0 = f[(size_t)lane * P_];
    float v1 = f[(size_t)(lane + 32) * P_];
    float ss = v0 * v0 + v1 * v1;
    #pragma unroll
    for (int o = 16; o; o >>= 1) ss += __shfl_xor_sync(0xFFFFFFFFu, ss, o);
    float inv = 1.0f / fmaxf(sqrtf(ss), 1e-12f);
    float* out = g_fsn + (size_t)gw * C_;
    out[lane]      = v0 * inv;
    out[lane + 32] = v1 * inv;
    if (lane == 0) g_ys[gw] = labels[b * P_ + p];
}

// -------- contrastive loss: thread-per-row, smem j-tiles --------
__global__ void __launch_bounds__(128) loss_kernel() {
    int b = blockIdx.y;
    int t = threadIdx.x;
    int i = blockIdx.x * 128 + t;

    __shared__ float4 tile[128][16];
    __shared__ signed char ysm[K_];
    for (int q = t; q < K_; q += 128) ysm[q] = (signed char)g_ys[b * K_ + q];

    float4 myrow[16];
    const float4* fr = (const float4*)(g_fsn + ((size_t)b * K_ + i) * C_);
    #pragma unroll
    for (int q = 0; q < 16; ++q) myrow[q] = fr[q];
    int yi = g_ys[b * K_ + i];

    float d = 0.0f, pp = 0.0f;
    int pcnt = 0;

    for (int tb = 0; tb < 16; ++tb) {
        __syncthreads();
        const float4* src = (const float4*)(g_fsn + ((size_t)b * K_ + tb * 128) * C_);
        for (int q = t; q < 128 * 16; q += 128) ((float4*)tile)[q] = src[q];
        __syncthreads();
        int jb = tb * 128;
        for (int jj = 0; jj < 128; ++jj) {
            int j = jb + jj;
            if (j == i) continue;
            float acc = 0.0f;
            #pragma unroll
            for (int q = 0; q < 16; ++q) {
                float4 a = myrow[q], bb = tile[jj][q];
                acc = fmaf(a.x, bb.x, acc);
                acc = fmaf(a.y, bb.y, acc);
                acc = fmaf(a.z, bb.z, acc);
                acc = fmaf(a.w, bb.w, acc);
            }
            // fixed shift 1/T (== row max up to 1e-7): ratio p/d is shift-invariant
            float e = expf((acc - 1.0f) * INV_T);
            d += e;
            if ((int)ysm[j] == yi) { pp += e; pcnt++; }
        }
    }

    if (yi == 1 && pcnt > 0) {
        float loss = logf(fmaxf(d, 1e-8f)) - logf(fmaxf(pp, 1e-8f));
        atomicAdd(&g_loss_sum[b], loss);
        atomicAdd(&g_valid[b], 1);
    }
}

__global__ void final_kernel(float* out) {
    float s = 0.0f;
    for (int b = 0; b < B_; ++b) {
        int v = g_valid[b]; if (v < 1) v = 1;
        s += g_loss_sum[b] / (float)v;
    }
    out[0] = s / (float)B_;
}

// -------- launch --------
extern "C" void kernel_launch(void* const* d_in, const int* in_sizes, int n_in,
                              void* d_out, int out_size) {
    const float* feats  = (const float*)d_in[0];
    const int*   labels = (const int*)d_in[1];

    // Derive JAX keys host-side (deterministic; baked into graph as kernel args).
    // root = key(1) = [0,1]; split(root, 8): counts iota(16); split(key_b, 3): counts iota(6).
    KeyArg ka;
    uint32_t out16[16];
    for (int j = 0; j < 8; ++j)
        tf2x32(0u, 1u, (uint32_t)j, (uint32_t)(8 + j), out16[j], out16[8 + j]);
    for (int b = 0; b < B_; ++b) {
        uint32_t kb0 = out16[2 * b], kb1 = out16[2 * b + 1];
        uint32_t o6[6];
        for (int j = 0; j < 3; ++j)
            tf2x32(kb0, kb1, (uint32_t)j, (uint32_t)(3 + j), o6[j], o6[3 + j]);
        ka.k[b][0][0] = o6[0]; ka.k[b][0][1] = o6[1];   // k1 -> fg pick
        ka.k[b][1][0] = o6[2]; ka.k[b][1][1] = o6[3];   // k2 -> ring pick
        ka.k[b][2][0] = o6[4]; ka.k[b][2][1] = o6[5];   // k3 -> bg pick
    }

    init_kernel<<<1, 32>>>();
    dim3 gmask(H_, B_);
    rowdil_kernel<<<gmask, W_>>>(labels);
    coldil_kernel<<<gmask, W_>>>();
    select_kernel<<<24, 1024>>>(ka);
    gather_kernel<<<(B_ * K_ * 32 + 255) / 256, 256>>>(feats, labels);
    dim3 gloss(16, B_);
    loss_kernel<<<gloss, 128>>>();
    final_kernel<<<1, 1>>>((float*)d_out);
}

// round 3
// speedup vs baseline: 2.2939x; 2.2939x over previous
#include <cuda_runtime.h>
#include <cstdint>
#include <math.h>

#define B_ 8
#define C_ 64
#define H_ 256
#define W_ 256
#define P_ (H_*W_)
#define K_ 2048
#define NFG 1024
#define NHARD 768
#define NRAND 256
#define RADIUS_ 10
#define INV_T (1.0f/0.07f)
#define NG 24              // B_ * 3 picks
#define JSPLIT 8
#define JCHUNK (K_/JSPLIT) // 256

// -------- scratch (static __device__, no allocations) --------
__device__ unsigned char g_rowdil[B_*P_];
__device__ unsigned char g_cat[B_*P_];          // bit0 = fg, bit1 = dilated
__device__ uint32_t g_u[NG][P_];                // cached uniforms (L2-resident)
__device__ unsigned int g_hist[NG][2048];
__device__ int g_bstar[NG];
__device__ int g_r[NG];
__device__ unsigned long long g_cand[NG][4096];
__device__ int g_ccnt[NG];
__device__ int g_ocnt[NG];
__device__ int   g_idx[B_*K_];
__device__ int   g_ys [B_*K_];
__device__ float g_fsn[B_*K_*C_];
__device__ float g_d [B_*K_*JSPLIT];            // deterministic partials
__device__ float g_pp[B_*K_*JSPLIT];
__device__ float g_loss_sum[B_];
__device__ int   g_valid[B_];

// -------- Threefry-2x32 (matches JAX threefry2x32 exactly) --------
__host__ __device__ inline void tf2x32(uint32_t k0, uint32_t k1,
                                       uint32_t x0, uint32_t x1,
                                       uint32_t& o0, uint32_t& o1) {
    uint32_t ks2 = k0 ^ k1 ^ 0x1BD11BDAu;
    x0 += k0; x1 += k1;
#define RR(r) { x0 += x1; x1 = (x1 << r) | (x1 >> (32 - r)); x1 ^= x0; }
    RR(13) RR(15) RR(26) RR(6)  x0 += k1;  x1 += ks2 + 1u;
    RR(17) RR(29) RR(16) RR(24) x0 += ks2; x1 += k0  + 2u;
    RR(13) RR(15) RR(26) RR(6)  x0 += k0;  x1 += k1  + 3u;
    RR(17) RR(29) RR(16) RR(24) x0 += k1;  x1 += ks2 + 4u;
    RR(13) RR(15) RR(26) RR(6)  x0 += ks2; x1 += k0  + 5u;
#undef RR
    o0 = x0; o1 = x1;
}

__device__ __forceinline__ bool inmask(int pick, unsigned char c) {
    unsigned char m = c & 3;
    return (pick == 0) ? (m & 1) : (pick == 1) ? (m == 2) : (m == 0);
}

// -------- init: zero histograms + counters --------
#define NZERO (NG*2048 + NG + NG)
__global__ void init_zero() {
    int i = blockIdx.x * blockDim.x + threadIdx.x;
    if (i < NG*2048) { ((unsigned int*)g_hist)[i] = 0u; return; }
    i -= NG*2048;
    if (i < NG) { g_ccnt[i] = 0; return; }
    i -= NG;
    if (i < NG) { g_ocnt[i] = 0; return; }
}

// -------- masks: separable 21x21 max-pool dilation --------
__global__ void rowdil_kernel(const int* __restrict__ labels) {
    int b = blockIdx.y, i = blockIdx.x, j = threadIdx.x;
    __shared__ unsigned char row[W_];
    int p = i * W_ + j;
    int fg = (labels[b * P_ + p] == 1);
    row[j] = (unsigned char)fg;
    __syncthreads();
    int lo = j - RADIUS_; if (lo < 0) lo = 0;
    int hi = j + RADIUS_; if (hi > W_ - 1) hi = W_ - 1;
    unsigned char od = 0;
    for (int jj = lo; jj <= hi; ++jj) od |= row[jj];
    g_rowdil[b * P_ + p] = od;
    g_cat[b * P_ + p] = (unsigned char)fg;
}

__global__ void coldil_kernel() {
    int b = blockIdx.y, i = blockIdx.x, j = threadIdx.x;
    int lo = i - RADIUS_; if (lo < 0) lo = 0;
    int hi = i + RADIUS_; if (hi > H_ - 1) hi = H_ - 1;
    unsigned char d = 0;
    for (int ii = lo; ii <= hi; ++ii) d |= g_rowdil[b * P_ + ii * W_ + j];
    int p = i * W_ + j;
    if (d) g_cat[b * P_ + p] |= 2;
}

// -------- selection stage 1: hash + histogram (grid NG x 8, 256 thr) --------
struct KeyArg { uint32_t k[B_][3][2]; };

__global__ void __launch_bounds__(256) hash_hist_kernel(KeyArg ka) {
    int g = blockIdx.x, chunk = blockIdx.y;
    int b = g / 3, pick = g % 3;
    uint32_t k0 = ka.k[b][pick][0], k1 = ka.k[b][pick][1];
    int t = threadIdx.x;
    __shared__ unsigned int h[2048];
    for (int q = t; q < 2048; q += 256) h[q] = 0u;
    __syncthreads();
    const unsigned char* cat = g_cat + b * P_;
    for (int kk = 0; kk < 16; ++kk) {
        int j = chunk * 4096 + kk * 256 + t;
        uint32_t o0, o1;
        tf2x32(k0, k1, (uint32_t)j, (uint32_t)(j + 32768), o0, o1);
        g_u[g][j] = o0;
        g_u[g][j + 32768] = o1;
        if (inmask(pick, cat[j]))         atomicAdd(&h[o0 >> 21], 1u);
        if (inmask(pick, cat[j + 32768])) atomicAdd(&h[o1 >> 21], 1u);
    }
    __syncthreads();
    for (int q = t; q < 2048; q += 256)
        if (h[q]) atomicAdd(&g_hist[g][q], h[q]);
}

// -------- selection stage 2: find boundary bin (grid NG, 256 thr) --------
__global__ void __launch_bounds__(256) scan_kernel() {
    int g = blockIdx.x, t = threadIdx.x;
    int pick = g % 3;
    int n = (pick == 0) ? NFG : (pick == 1) ? NHARD : NRAND;
    __shared__ unsigned int h[2048];
    __shared__ unsigned int part[256];
    for (int q = t; q < 2048; q += 256) h[q] = g_hist[g][q];
    __syncthreads();
    unsigned int s8 = 0;
    #pragma unroll
    for (int k = 0; k < 8; ++k) s8 += h[2047 - (t * 8 + k)];
    part[t] = s8;
    __syncthreads();
    if (t == 0) {
        int cum = 0, seg = 0;
        while (seg < 256 && cum + (int)part[seg] < n) { cum += (int)part[seg]; seg++; }
        int bstar = 0, above = cum;
        for (int k = 0; k < 8; ++k) {
            int q = 2047 - (seg * 8 + k);
            int hh = (int)h[q];
            if (cum + hh >= n) { bstar = q; above = cum; break; }
            cum += hh;
        }
        g_bstar[g] = bstar;
        g_r[g] = n - above;   // slots to fill from boundary bin
    }
}

// -------- selection stage 3: emit (grid NG x 8, 256 thr) --------
// covers BOTH halves of the counter space (p and p+32768) — the round-2 bug
__global__ void __launch_bounds__(256) emit_kernel() {
    int g = blockIdx.x, chunk = blockIdx.y;
    int b = g / 3, pick = g % 3;
    int base = b * K_ + ((pick == 0) ? 0 : (pick == 1) ? NFG : (NFG + NHARD));
    int bstar = g_bstar[g];
    int t = threadIdx.x;
    const unsigned char* cat = g_cat + b * P_;
    for (int kk = 0; kk < 16; ++kk) {
        int p0 = chunk * 4096 + kk * 256 + t;
        #pragma unroll
        for (int hh = 0; hh < 2; ++hh) {
            int p = p0 + hh * 32768;
            uint32_t u = g_u[g][p];
            if (inmask(pick, cat[p])) {
                int bin = (int)(u >> 21);
                if (bin > bstar) {
                    int slot = atomicAdd(&g_ocnt[g], 1);
                    g_idx[base + slot] = p;
                } else if (bin == bstar) {
                    int c = atomicAdd(&g_ccnt[g], 1);
                    if (c < 4096)
                        // value desc, then index asc (top_k tie rule)
                        g_cand[g][c] = ((unsigned long long)(u >> 9) << 16)
                                     | (unsigned long long)(0xFFFFu - (uint32_t)p);
                }
            }
        }
    }
}

// -------- selection stage 4: boundary-bin rank select (grid NG, 256 thr) ----
__global__ void __launch_bounds__(256) boundary_kernel() {
    int g = blockIdx.x, t = threadIdx.x;
    int b = g / 3, pick = g % 3;
    int base = b * K_ + ((pick == 0) ? 0 : (pick == 1) ? NFG : (NFG + NHARD));
    int c = g_ccnt[g]; if (c > 4096) c = 4096;
    int r = g_r[g];
    __shared__ unsigned long long cd[4096];
    for (int ci = t; ci < c; ci += 256) cd[ci] = g_cand[g][ci];
    __syncthreads();
    for (int ci = t; ci < c; ci += 256) {
        unsigned long long v = cd[ci];
        int rank = 0;
        for (int q = 0; q < c; ++q) rank += (cd[q] > v);
        if (rank < r) {
            int slot = atomicAdd(&g_ocnt[g], 1);
            g_idx[base + slot] = 0xFFFF - (int)(v & 0xFFFFull);
        }
    }
}

// -------- gather + L2-normalize (one warp per sample) --------
__global__ void gather_kernel(const float* __restrict__ feats,
                              const int* __restrict__ labels) {
    int gw   = (blockIdx.x * blockDim.x + threadIdx.x) >> 5;
    int lane = threadIdx.x & 31;
    if (gw >= B_ * K_) return;
    int b = gw / K_;
    int p = g_idx[gw];
    const float* f = feats + (size_t)b * C_ * P_ + p;
    float v0 = f[(size_t)lane * P_];
    float v1 = f[(size_t)(lane + 32) * P_];
    float ss = v0 * v0 + v1 * v1;
    #pragma unroll
    for (int o = 16; o; o >>= 1) ss += __shfl_xor_sync(0xFFFFFFFFu, ss, o);
    float inv = 1.0f / fmaxf(sqrtf(ss), 1e-12f);
    float* out = g_fsn + (size_t)gw * C_;
    out[lane]      = v0 * inv;
    out[lane + 32] = v1 * inv;
    if (lane == 0) g_ys[gw] = labels[b * P_ + p];
}

// -------- contrastive loss partials: thread-per-row, j-split 8 ways --------
// partials land in disjoint slots (no atomics -> deterministic)
__global__ void __launch_bounds__(128) loss_kernel() {
    int b  = blockIdx.z;
    int ib = blockIdx.y;
    int js = blockIdx.x;
    int t  = threadIdx.x;
    int i  = ib * 128 + t;
    int jbase = js * JCHUNK;

    __shared__ float4 tile[128][16];
    __shared__ signed char ysm[JCHUNK];
    for (int q = t; q < JCHUNK; q += 128) ysm[q] = (signed char)g_ys[b * K_ + jbase + q];

    float4 myrow[16];
    const float4* fr = (const float4*)(g_fsn + ((size_t)b * K_ + i) * C_);
    #pragma unroll
    for (int q = 0; q < 16; ++q) myrow[q] = fr[q];
    int yi = g_ys[b * K_ + i];

    float dsum = 0.0f, psum = 0.0f;

    for (int tb = 0; tb < JCHUNK / 128; ++tb) {
        __syncthreads();
        const float4* src = (const float4*)(g_fsn + ((size_t)b * K_ + jbase + tb * 128) * C_);
        for (int q = t; q < 128 * 16; q += 128) ((float4*)tile)[q] = src[q];
        __syncthreads();
        int j0 = jbase + tb * 128;
        for (int jj = 0; jj < 128; ++jj) {
            int j = j0 + jj;
            if (j == i) continue;
            float acc = 0.0f;
            #pragma unroll
            for (int q = 0; q < 16; ++q) {
                float4 a = myrow[q], bb = tile[jj][q];
                acc = fmaf(a.x, bb.x, acc);
                acc = fmaf(a.y, bb.y, acc);
                acc = fmaf(a.z, bb.z, acc);
                acc = fmaf(a.w, bb.w, acc);
            }
            // fixed shift 1/T (== row max incl. diagonal): ratio is shift-invariant
            float e = expf((acc - 1.0f) * INV_T);
            dsum += e;
            psum += ((int)ysm[tb * 128 + jj] == yi) ? e : 0.0f;
        }
    }

    g_d [(b * K_ + i) * JSPLIT + js] = dsum;
    g_pp[(b * K_ + i) * JSPLIT + js] = psum;
}

// -------- per-row loss + per-image reduce (fixed summation order) --------
__global__ void __launch_bounds__(256) rowloss_kernel() {
    int b = blockIdx.x, t = threadIdx.x;
    float ls = 0.0f; int cnt = 0;
    for (int i = t; i < K_; i += 256) {
        int yi = g_ys[b * K_ + i];
        float dv = 0.0f, pv = 0.0f;
        #pragma unroll
        for (int js = 0; js < JSPLIT; ++js) {
            dv += g_d [(b * K_ + i) * JSPLIT + js];
            pv += g_pp[(b * K_ + i) * JSPLIT + js];
        }
        if (yi == 1 && pv > 0.0f) {
            ls += logf(fmaxf(dv, 1e-8f)) - logf(fmaxf(pv, 1e-8f));
            cnt++;
        }
    }
    __shared__ float ss[256];
    __shared__ int   sc[256];
    ss[t] = ls; sc[t] = cnt;
    __syncthreads();
    for (int o = 128; o; o >>= 1) {
        if (t < o) { ss[t] += ss[t + o]; sc[t] += sc[t + o]; }
        __syncthreads();
    }
    if (t == 0) { g_loss_sum[b] = ss[0]; g_valid[b] = sc[0]; }
}

__global__ void final_kernel(float* out) {
    float s = 0.0f;
    for (int b = 0; b < B_; ++b) {
        int v = g_valid[b]; if (v < 1) v = 1;
        s += g_loss_sum[b] / (float)v;
    }
    out[0] = s / (float)B_;
}

// -------- launch --------
extern "C" void kernel_launch(void* const* d_in, const int* in_sizes, int n_in,
                              void* d_out, int out_size) {
    const float* feats  = (const float*)d_in[0];
    const int*   labels = (const int*)d_in[1];

    // Derive JAX keys host-side (deterministic; baked into graph as kernel args).
    // root = key(1) = [0,1]; split(root, 8): counts iota(16); split(key_b, 3): iota(6).
    KeyArg ka;
    uint32_t out16[16];
    for (int j = 0; j < 8; ++j)
        tf2x32(0u, 1u, (uint32_t)j, (uint32_t)(8 + j), out16[j], out16[8 + j]);
    for (int b = 0; b < B_; ++b) {
        uint32_t kb0 = out16[2 * b], kb1 = out16[2 * b + 1];
        uint32_t o6[6];
        for (int j = 0; j < 3; ++j)
            tf2x32(kb0, kb1, (uint32_t)j, (uint32_t)(3 + j), o6[j], o6[3 + j]);
        ka.k[b][0][0] = o6[0]; ka.k[b][0][1] = o6[1];   // k1 -> fg pick
        ka.k[b][1][0] = o6[2]; ka.k[b][1][1] = o6[3];   // k2 -> ring pick
        ka.k[b][2][0] = o6[4]; ka.k[b][2][1] = o6[5];   // k3 -> bg pick
    }

    init_zero<<<(NZERO + 255) / 256, 256>>>();
    dim3 gmask(H_, B_);
    rowdil_kernel<<<gmask, W_>>>(labels);
    coldil_kernel<<<gmask, W_>>>();
    hash_hist_kernel<<<dim3(NG, 8), 256>>>(ka);
    scan_kernel<<<NG, 256>>>();
    emit_kernel<<<dim3(NG, 8), 256>>>();
    boundary_kernel<<<NG, 256>>>();
    gather_kernel<<<(B_ * K_ * 32 + 255) / 256, 256>>>(feats, labels);
    loss_kernel<<<dim3(JSPLIT, 16, B_), 128>>>();
    rowloss_kernel<<<B_, 256>>>();
    final_kernel<<<1, 1>>>((float*)d_out);
}

// round 5
// speedup vs baseline: 2.5989x; 1.1330x over previous
#include <cuda_runtime.h>
#include <cstdint>
#include <math.h>

#define B_ 8
#define C_ 64
#define H_ 256
#define W_ 256
#define P_ (H_*W_)
#define K_ 2048
#define NFG 1024
#define NHARD 768
#define NRAND 256
#define RADIUS_ 10
#define INV_T (1.0f/0.07f)
#define NG 24              // B_ * 3 picks
#define JSPLIT 8
#define JCHUNK (K_/JSPLIT) // 256

// -------- scratch (static __device__, no allocations) --------
__device__ unsigned char g_rowdil[B_*P_];
__device__ unsigned char g_cat[B_*P_];          // bit0 = fg, bit1 = dilated
__device__ uint32_t g_u[NG][P_];                // cached uniforms (L2-resident)
__device__ unsigned int g_hist[NG][2048];
__device__ int g_bstar[NG];
__device__ int g_r[NG];
__device__ unsigned long long g_cand[NG][4096];
__device__ int g_ccnt[NG];
__device__ int g_ocnt[NG];
__device__ int   g_idx[B_*K_];
__device__ int   g_ys [B_*K_];
__device__ float g_fsn[B_*K_*C_];
__device__ float g_d [B_*K_*JSPLIT];            // deterministic partials
__device__ float g_pp[B_*K_*JSPLIT];
__device__ float g_loss_sum[B_];
__device__ int   g_valid[B_];

// -------- packed f32x2 FMA (Blackwell sm_103a) --------
__device__ __forceinline__ unsigned long long ffma2(unsigned long long a,
                                                    unsigned long long b,
                                                    unsigned long long c) {
    unsigned long long d;
    asm("fma.rn.f32x2 %0, %1, %2, %3;" : "=l"(d) : "l"(a), "l"(b), "l"(c));
    return d;
}
__device__ __forceinline__ void unpack2(unsigned long long v, float& lo, float& hi) {
    asm("mov.b64 {%0, %1}, %2;" : "=f"(lo), "=f"(hi) : "l"(v));
}

// -------- Threefry-2x32 (matches JAX threefry2x32 exactly) --------
__host__ __device__ inline void tf2x32(uint32_t k0, uint32_t k1,
                                       uint32_t x0, uint32_t x1,
                                       uint32_t& o0, uint32_t& o1) {
    uint32_t ks2 = k0 ^ k1 ^ 0x1BD11BDAu;
    x0 += k0; x1 += k1;
#define RR(r) { x0 += x1; x1 = (x1 << r) | (x1 >> (32 - r)); x1 ^= x0; }
    RR(13) RR(15) RR(26) RR(6)  x0 += k1;  x1 += ks2 + 1u;
    RR(17) RR(29) RR(16) RR(24) x0 += ks2; x1 += k0  + 2u;
    RR(13) RR(15) RR(26) RR(6)  x0 += k0;  x1 += k1  + 3u;
    RR(17) RR(29) RR(16) RR(24) x0 += k1;  x1 += ks2 + 4u;
    RR(13) RR(15) RR(26) RR(6)  x0 += ks2; x1 += k0  + 5u;
#undef RR
    o0 = x0; o1 = x1;
}

__device__ __forceinline__ bool inmask(int pick, unsigned char c) {
    unsigned char m = c & 3;
    return (pick == 0) ? (m & 1) : (pick == 1) ? (m == 2) : (m == 0);
}

// -------- init: zero histograms + counters --------
#define NZERO (NG*2048 + NG + NG)
__global__ void init_zero() {
    int i = blockIdx.x * blockDim.x + threadIdx.x;
    if (i < NG*2048) { ((unsigned int*)g_hist)[i] = 0u; return; }
    i -= NG*2048;
    if (i < NG) { g_ccnt[i] = 0; return; }
    i -= NG;
    if (i < NG) { g_ocnt[i] = 0; return; }
}

// -------- masks: separable 21x21 max-pool dilation --------
__global__ void rowdil_kernel(const int* __restrict__ labels) {
    int b = blockIdx.y, i = blockIdx.x, j = threadIdx.x;
    __shared__ unsigned char row[W_];
    int p = i * W_ + j;
    int fg = (labels[b * P_ + p] == 1);
    row[j] = (unsigned char)fg;
    __syncthreads();
    int lo = j - RADIUS_; if (lo < 0) lo = 0;
    int hi = j + RADIUS_; if (hi > W_ - 1) hi = W_ - 1;
    unsigned char od = 0;
    for (int jj = lo; jj <= hi; ++jj) od |= row[jj];
    g_rowdil[b * P_ + p] = od;
    g_cat[b * P_ + p] = (unsigned char)fg;
}

__global__ void coldil_kernel() {
    int b = blockIdx.y, i = blockIdx.x, j = threadIdx.x;
    int lo = i - RADIUS_; if (lo < 0) lo = 0;
    int hi = i + RADIUS_; if (hi > H_ - 1) hi = H_ - 1;
    unsigned char d = 0;
    for (int ii = lo; ii <= hi; ++ii) d |= g_rowdil[b * P_ + ii * W_ + j];
    int p = i * W_ + j;
    if (d) g_cat[b * P_ + p] |= 2;
}

// -------- selection stage 1: hash + histogram (grid NG x 32, 256 thr) -------
struct KeyArg { uint32_t k[B_][3][2]; };

__global__ void __launch_bounds__(256) hash_hist_kernel(KeyArg ka) {
    int g = blockIdx.x, chunk = blockIdx.y;
    int b = g / 3, pick = g % 3;
    uint32_t k0 = ka.k[b][pick][0], k1 = ka.k[b][pick][1];
    int t = threadIdx.x;
    __shared__ unsigned int h[2048];
    for (int q = t; q < 2048; q += 256) h[q] = 0u;
    __syncthreads();
    const unsigned char* cat = g_cat + b * P_;
    for (int kk = 0; kk < 4; ++kk) {
        int j = chunk * 1024 + kk * 256 + t;
        uint32_t o0, o1;
        tf2x32(k0, k1, (uint32_t)j, (uint32_t)(j + 32768), o0, o1);
        g_u[g][j] = o0;
        g_u[g][j + 32768] = o1;
        if (inmask(pick, cat[j]))         atomicAdd(&h[o0 >> 21], 1u);
        if (inmask(pick, cat[j + 32768])) atomicAdd(&h[o1 >> 21], 1u);
    }
    __syncthreads();
    for (int q = t; q < 2048; q += 256)
        if (h[q]) atomicAdd(&g_hist[g][q], h[q]);
}

// -------- selection stage 2: find boundary bin (grid NG, 256 thr) --------
__global__ void __launch_bounds__(256) scan_kernel() {
    int g = blockIdx.x, t = threadIdx.x;
    int pick = g % 3;
    int n = (pick == 0) ? NFG : (pick == 1) ? NHARD : NRAND;
    __shared__ unsigned int h[2048];
    __shared__ unsigned int part[256];
    for (int q = t; q < 2048; q += 256) h[q] = g_hist[g][q];
    __syncthreads();
    unsigned int s8 = 0;
    #pragma unroll
    for (int k = 0; k < 8; ++k) s8 += h[2047 - (t * 8 + k)];
    part[t] = s8;
    __syncthreads();
    if (t == 0) {
        int cum = 0, seg = 0;
        while (seg < 256 && cum + (int)part[seg] < n) { cum += (int)part[seg]; seg++; }
        int bstar = 0, above = cum;
        for (int k = 0; k < 8; ++k) {
            int q = 2047 - (seg * 8 + k);
            int hh = (int)h[q];
            if (cum + hh >= n) { bstar = q; above = cum; break; }
            cum += hh;
        }
        g_bstar[g] = bstar;
        g_r[g] = n - above;   // slots to fill from boundary bin
    }
}

// -------- selection stage 3: emit (grid NG x 32, 256 thr) --------
// covers BOTH halves of the counter space (p and p+32768)
__global__ void __launch_bounds__(256) emit_kernel() {
    int g = blockIdx.x, chunk = blockIdx.y;
    int b = g / 3, pick = g % 3;
    int base = b * K_ + ((pick == 0) ? 0 : (pick == 1) ? NFG : (NFG + NHARD));
    int bstar = g_bstar[g];
    int t = threadIdx.x;
    const unsigned char* cat = g_cat + b * P_;
    for (int kk = 0; kk < 4; ++kk) {
        int p0 = chunk * 1024 + kk * 256 + t;
        #pragma unroll
        for (int hh = 0; hh < 2; ++hh) {
            int p = p0 + hh * 32768;
            uint32_t u = g_u[g][p];
            if (inmask(pick, cat[p])) {
                int bin = (int)(u >> 21);
                if (bin > bstar) {
                    int slot = atomicAdd(&g_ocnt[g], 1);
                    g_idx[base + slot] = p;
                } else if (bin == bstar) {
                    int c = atomicAdd(&g_ccnt[g], 1);
                    if (c < 4096)
                        // value desc, then index asc (top_k tie rule)
                        g_cand[g][c] = ((unsigned long long)(u >> 9) << 16)
                                     | (unsigned long long)(0xFFFFu - (uint32_t)p);
                }
            }
        }
    }
}

// -------- selection stage 4: boundary-bin rank select (grid NG, 256 thr) ----
__global__ void __launch_bounds__(256) boundary_kernel() {
    int g = blockIdx.x, t = threadIdx.x;
    int b = g / 3, pick = g % 3;
    int base = b * K_ + ((pick == 0) ? 0 : (pick == 1) ? NFG : (NFG + NHARD));
    int c = g_ccnt[g]; if (c > 4096) c = 4096;
    int r = g_r[g];
    __shared__ unsigned long long cd[4096];
    for (int ci = t; ci < c; ci += 256) cd[ci] = g_cand[g][ci];
    __syncthreads();
    for (int ci = t; ci < c; ci += 256) {
        unsigned long long v = cd[ci];
        int rank = 0;
        for (int q = 0; q < c; ++q) rank += (cd[q] > v);
        if (rank < r) {
            int slot = atomicAdd(&g_ocnt[g], 1);
            g_idx[base + slot] = 0xFFFF - (int)(v & 0xFFFFull);
        }
    }
}

// -------- gather + L2-normalize (one warp per sample) --------
__global__ void gather_kernel(const float* __restrict__ feats,
                              const int* __restrict__ labels) {
    int gw   = (blockIdx.x * blockDim.x + threadIdx.x) >> 5;
    int lane = threadIdx.x & 31;
    if (gw >= B_ * K_) return;
    int b = gw / K_;
    int p = g_idx[gw];
    const float* f = feats + (size_t)b * C_ * P_ + p;
    float v0 = f[(size_t)lane * P_];
    float v1 = f[(size_t)(lane + 32) * P_];
    float ss = v0 * v0 + v1 * v1;
    #pragma unroll
    for (int o = 16; o; o >>= 1) ss += __shfl_xor_sync(0xFFFFFFFFu, ss, o);
    float inv = 1.0f / fmaxf(sqrtf(ss), 1e-12f);
    float* out = g_fsn + (size_t)gw * C_;
    out[lane]      = v0 * inv;
    out[lane + 32] = v1 * inv;
    if (lane == 0) g_ys[gw] = labels[b * P_ + p];
}

// -------- contrastive loss partials: f32x2 packed dot (FULL 64-ch row) ------
// partials land in disjoint slots (no atomics -> deterministic)
__global__ void __launch_bounds__(128) loss_kernel() {
    int b  = blockIdx.z;
    int ib = blockIdx.y;
    int js = blockIdx.x;
    int t  = threadIdx.x;
    int i  = ib * 128 + t;
    int jbase = js * JCHUNK;

    __shared__ ulonglong2 tile[128][16];    // 128 rows x 64 ch (256 B/row) = 32 KB
    __shared__ signed char ysm[JCHUNK];
    for (int q = t; q < JCHUNK; q += 128) ysm[q] = (signed char)g_ys[b * K_ + jbase + q];

    ulonglong2 myrow[16];                   // 16 x 16 B = 256 B = 64 floats
    const ulonglong2* fr = (const ulonglong2*)(g_fsn + ((size_t)b * K_ + i) * C_);
    #pragma unroll
    for (int q = 0; q < 16; ++q) myrow[q] = fr[q];
    int yi = g_ys[b * K_ + i];

    float dsum = 0.0f, psum = 0.0f;

    for (int tb = 0; tb < JCHUNK / 128; ++tb) {
        __syncthreads();
        const ulonglong2* src =
            (const ulonglong2*)(g_fsn + ((size_t)b * K_ + jbase + tb * 128) * C_);
        for (int q = t; q < 128 * 16; q += 128) ((ulonglong2*)tile)[q] = src[q];
        __syncthreads();
        int j0 = jbase + tb * 128;
        for (int jj = 0; jj < 128; ++jj) {
            int j = j0 + jj;
            if (j == i) continue;
            // 4 packed accumulator chains, each 8 FFMA2 deep
            unsigned long long a0 = 0ull, a1 = 0ull, a2 = 0ull, a3 = 0ull;
            #pragma unroll
            for (int q = 0; q < 16; q += 2) {
                ulonglong2 tv0 = tile[jj][q];
                ulonglong2 tv1 = tile[jj][q + 1];
                a0 = ffma2(myrow[q].x,     tv0.x, a0);
                a1 = ffma2(myrow[q].y,     tv0.y, a1);
                a2 = ffma2(myrow[q + 1].x, tv1.x, a2);
                a3 = ffma2(myrow[q + 1].y, tv1.y, a3);
            }
            float l0, h0, l1, h1, l2, h2, l3, h3;
            unpack2(a0, l0, h0); unpack2(a1, l1, h1);
            unpack2(a2, l2, h2); unpack2(a3, l3, h3);
            float acc = ((l0 + h0) + (l1 + h1)) + ((l2 + h2) + (l3 + h3));
            // fixed shift 1/T (== row max incl. diagonal): ratio is shift-invariant
            float e = expf((acc - 1.0f) * INV_T);
            dsum += e;
            psum += ((int)ysm[tb * 128 + jj] == yi) ? e : 0.0f;
        }
    }

    g_d [(b * K_ + i) * JSPLIT + js] = dsum;
    g_pp[(b * K_ + i) * JSPLIT + js] = psum;
}

// -------- per-row loss + per-image reduce (fixed summation order) --------
__global__ void __launch_bounds__(256) rowloss_kernel() {
    int b = blockIdx.x, t = threadIdx.x;
    float ls = 0.0f; int cnt = 0;
    for (int i = t; i < K_; i += 256) {
        int yi = g_ys[b * K_ + i];
        float dv = 0.0f, pv = 0.0f;
        #pragma unroll
        for (int js = 0; js < JSPLIT; ++js) {
            dv += g_d [(b * K_ + i) * JSPLIT + js];
            pv += g_pp[(b * K_ + i) * JSPLIT + js];
        }
        if (yi == 1 && pv > 0.0f) {
            ls += logf(fmaxf(dv, 1e-8f)) - logf(fmaxf(pv, 1e-8f));
            cnt++;
        }
    }
    __shared__ float ss[256];
    __shared__ int   sc[256];
    ss[t] = ls; sc[t] = cnt;
    __syncthreads();
    for (int o = 128; o; o >>= 1) {
        if (t < o) { ss[t] += ss[t + o]; sc[t] += sc[t + o]; }
        __syncthreads();
    }
    if (t == 0) { g_loss_sum[b] = ss[0]; g_valid[b] = sc[0]; }
}

__global__ void final_kernel(float* out) {
    float s = 0.0f;
    for (int b = 0; b < B_; ++b) {
        int v = g_valid[b]; if (v < 1) v = 1;
        s += g_loss_sum[b] / (float)v;
    }
    out[0] = s / (float)B_;
}

// -------- launch --------
extern "C" void kernel_launch(void* const* d_in, const int* in_sizes, int n_in,
                              void* d_out, int out_size) {
    const float* feats  = (const float*)d_in[0];
    const int*   labels = (const int*)d_in[1];

    // Derive JAX keys host-side (deterministic; baked into graph as kernel args).
    KeyArg ka;
    uint32_t out16[16];
    for (int j = 0; j < 8; ++j)
        tf2x32(0u, 1u, (uint32_t)j, (uint32_t)(8 + j), out16[j], out16[8 + j]);
    for (int b = 0; b < B_; ++b) {
        uint32_t kb0 = out16[2 * b], kb1 = out16[2 * b + 1];
        uint32_t o6[6];
        for (int j = 0; j < 3; ++j)
            tf2x32(kb0, kb1, (uint32_t)j, (uint32_t)(3 + j), o6[j], o6[3 + j]);
        ka.k[b][0][0] = o6[0]; ka.k[b][0][1] = o6[1];   // k1 -> fg pick
        ka.k[b][1][0] = o6[2]; ka.k[b][1][1] = o6[3];   // k2 -> ring pick
        ka.k[b][2][0] = o6[4]; ka.k[b][2][1] = o6[5];   // k3 -> bg pick
    }

    init_zero<<<(NZERO + 255) / 256, 256>>>();
    dim3 gmask(H_, B_);
    rowdil_kernel<<<gmask, W_>>>(labels);
    coldil_kernel<<<gmask, W_>>>();
    hash_hist_kernel<<<dim3(NG, 32), 256>>>(ka);
    scan_kernel<<<NG, 256>>>();
    emit_kernel<<<dim3(NG, 32), 256>>>();
    boundary_kernel<<<NG, 256>>>();
    gather_kernel<<<(B_ * K_ * 32 + 255) / 256, 256>>>(feats, labels);
    loss_kernel<<<dim3(JSPLIT, 16, B_), 128>>>();
    rowloss_kernel<<<B_, 256>>>();
    final_kernel<<<1, 1>>>((float*)d_out);
}

// round 6
// speedup vs baseline: 5.0110x; 1.9281x over previous
#include <cuda_runtime.h>
#include <cstdint>
#include <math.h>

#define B_ 8
#define C_ 64
#define H_ 256
#define W_ 256
#define P_ (H_*W_)
#define K_ 2048
#define NFG 1024
#define NHARD 768
#define NRAND 256
#define RADIUS_ 10
#define NG 24              // B_ * 3 picks
#define NJT 16             // j-tiles per row (2048/128)
// exp((c-1)/T) = 2^(c*C1 + C0),  C1 = log2(e)/T
#define C1_ 20.609929155555663f
#define C0_ (-20.609929155555663f)

// -------- scratch (static __device__, no allocations) --------
__device__ unsigned char g_rowdil[B_*P_];
__device__ unsigned char g_cat[B_*P_];          // bit0 = fg, bit1 = dilated
__device__ uint32_t g_u[NG][P_];                // cached uniforms (L2-resident)
__device__ unsigned int g_hist[NG][2048];
__device__ int g_bstar[NG];
__device__ int g_r[NG];
__device__ unsigned long long g_cand[NG][4096];
__device__ int g_ccnt[NG];
__device__ int g_ocnt[NG];
__device__ int   g_idx[B_*K_];
__device__ int   g_ys [B_*K_];
__device__ float g_fsn[B_*K_*C_];               // tf32-rounded normalized feats
__device__ float g_d [B_*K_*NJT];               // deterministic partials
__device__ float g_pp[B_*K_*NJT];
__device__ float g_loss_sum[B_];
__device__ int   g_valid[B_];

// -------- small PTX helpers --------
__device__ __forceinline__ float ex2f(float x) {
    float y; asm("ex2.approx.f32 %0, %1;" : "=f"(y) : "f"(x)); return y;
}
__device__ __forceinline__ float to_tf32(float x) {
    uint32_t y; asm("cvt.rna.tf32.f32 %0, %1;" : "=r"(y) : "f"(x));
    return __uint_as_float(y);
}
__device__ __forceinline__ void mma_tf32(float c[4], const float a[4], const float b[2]) {
    asm volatile(
        "mma.sync.aligned.m16n8k8.row.col.f32.tf32.tf32.f32 "
        "{%0,%1,%2,%3}, {%4,%5,%6,%7}, {%8,%9}, {%0,%1,%2,%3};"
        : "+f"(c[0]), "+f"(c[1]), "+f"(c[2]), "+f"(c[3])
        : "r"(__float_as_uint(a[0])), "r"(__float_as_uint(a[1])),
          "r"(__float_as_uint(a[2])), "r"(__float_as_uint(a[3])),
          "r"(__float_as_uint(b[0])), "r"(__float_as_uint(b[1])));
}

// -------- Threefry-2x32 (matches JAX threefry2x32 exactly) --------
__host__ __device__ inline void tf2x32(uint32_t k0, uint32_t k1,
                                       uint32_t x0, uint32_t x1,
                                       uint32_t& o0, uint32_t& o1) {
    uint32_t ks2 = k0 ^ k1 ^ 0x1BD11BDAu;
    x0 += k0; x1 += k1;
#define RR(r) { x0 += x1; x1 = (x1 << r) | (x1 >> (32 - r)); x1 ^= x0; }
    RR(13) RR(15) RR(26) RR(6)  x0 += k1;  x1 += ks2 + 1u;
    RR(17) RR(29) RR(16) RR(24) x0 += ks2; x1 += k0  + 2u;
    RR(13) RR(15) RR(26) RR(6)  x0 += k0;  x1 += k1  + 3u;
    RR(17) RR(29) RR(16) RR(24) x0 += k1;  x1 += ks2 + 4u;
    RR(13) RR(15) RR(26) RR(6)  x0 += ks2; x1 += k0  + 5u;
#undef RR
    o0 = x0; o1 = x1;
}

__device__ __forceinline__ bool inmask(int pick, unsigned char c) {
    unsigned char m = c & 3;
    return (pick == 0) ? (m & 1) : (pick == 1) ? (m == 2) : (m == 0);
}

// -------- init: zero histograms + counters --------
#define NZERO (NG*2048 + NG + NG)
__global__ void init_zero() {
    int i = blockIdx.x * blockDim.x + threadIdx.x;
    if (i < NG*2048) { ((unsigned int*)g_hist)[i] = 0u; return; }
    i -= NG*2048;
    if (i < NG) { g_ccnt[i] = 0; return; }
    i -= NG;
    if (i < NG) { g_ocnt[i] = 0; return; }
}

// -------- masks: separable 21x21 max-pool dilation --------
__global__ void rowdil_kernel(const int* __restrict__ labels) {
    int b = blockIdx.y, i = blockIdx.x, j = threadIdx.x;
    __shared__ unsigned char row[W_];
    int p = i * W_ + j;
    int fg = (labels[b * P_ + p] == 1);
    row[j] = (unsigned char)fg;
    __syncthreads();
    int lo = j - RADIUS_; if (lo < 0) lo = 0;
    int hi = j + RADIUS_; if (hi > W_ - 1) hi = W_ - 1;
    unsigned char od = 0;
    for (int jj = lo; jj <= hi; ++jj) od |= row[jj];
    g_rowdil[b * P_ + p] = od;
    g_cat[b * P_ + p] = (unsigned char)fg;
}

__global__ void coldil_kernel() {
    int b = blockIdx.y, i = blockIdx.x, j = threadIdx.x;
    int lo = i - RADIUS_; if (lo < 0) lo = 0;
    int hi = i + RADIUS_; if (hi > H_ - 1) hi = H_ - 1;
    unsigned char d = 0;
    for (int ii = lo; ii <= hi; ++ii) d |= g_rowdil[b * P_ + ii * W_ + j];
    int p = i * W_ + j;
    if (d) g_cat[b * P_ + p] |= 2;
}

// -------- selection stage 1: hash + histogram (grid NG x 32, 256 thr) -------
struct KeyArg { uint32_t k[B_][3][2]; };

__global__ void __launch_bounds__(256) hash_hist_kernel(KeyArg ka) {
    int g = blockIdx.x, chunk = blockIdx.y;
    int b = g / 3, pick = g % 3;
    uint32_t k0 = ka.k[b][pick][0], k1 = ka.k[b][pick][1];
    int t = threadIdx.x;
    __shared__ unsigned int h[2048];
    for (int q = t; q < 2048; q += 256) h[q] = 0u;
    __syncthreads();
    const unsigned char* cat = g_cat + b * P_;
    for (int kk = 0; kk < 4; ++kk) {
        int j = chunk * 1024 + kk * 256 + t;
        uint32_t o0, o1;
        tf2x32(k0, k1, (uint32_t)j, (uint32_t)(j + 32768), o0, o1);
        g_u[g][j] = o0;
        g_u[g][j + 32768] = o1;
        if (inmask(pick, cat[j]))         atomicAdd(&h[o0 >> 21], 1u);
        if (inmask(pick, cat[j + 32768])) atomicAdd(&h[o1 >> 21], 1u);
    }
    __syncthreads();
    for (int q = t; q < 2048; q += 256)
        if (h[q]) atomicAdd(&g_hist[g][q], h[q]);
}

// -------- selection stage 2: find boundary bin (grid NG, 256 thr) --------
__global__ void __launch_bounds__(256) scan_kernel() {
    int g = blockIdx.x, t = threadIdx.x;
    int pick = g % 3;
    int n = (pick == 0) ? NFG : (pick == 1) ? NHARD : NRAND;
    __shared__ unsigned int h[2048];
    __shared__ unsigned int part[256];
    for (int q = t; q < 2048; q += 256) h[q] = g_hist[g][q];
    __syncthreads();
    unsigned int s8 = 0;
    #pragma unroll
    for (int k = 0; k < 8; ++k) s8 += h[2047 - (t * 8 + k)];
    part[t] = s8;
    __syncthreads();
    if (t == 0) {
        int cum = 0, seg = 0;
        while (seg < 256 && cum + (int)part[seg] < n) { cum += (int)part[seg]; seg++; }
        int bstar = 0, above = cum;
        for (int k = 0; k < 8; ++k) {
            int q = 2047 - (seg * 8 + k);
            int hh = (int)h[q];
            if (cum + hh >= n) { bstar = q; above = cum; break; }
            cum += hh;
        }
        g_bstar[g] = bstar;
        g_r[g] = n - above;   // slots to fill from boundary bin
    }
}

// -------- selection stage 3: emit (grid NG x 32, 256 thr) --------
__global__ void __launch_bounds__(256) emit_kernel() {
    int g = blockIdx.x, chunk = blockIdx.y;
    int b = g / 3, pick = g % 3;
    int base = b * K_ + ((pick == 0) ? 0 : (pick == 1) ? NFG : (NFG + NHARD));
    int bstar = g_bstar[g];
    int t = threadIdx.x;
    const unsigned char* cat = g_cat + b * P_;
    for (int kk = 0; kk < 4; ++kk) {
        int p0 = chunk * 1024 + kk * 256 + t;
        #pragma unroll
        for (int hh = 0; hh < 2; ++hh) {
            int p = p0 + hh * 32768;
            uint32_t u = g_u[g][p];
            if (inmask(pick, cat[p])) {
                int bin = (int)(u >> 21);
                if (bin > bstar) {
                    int slot = atomicAdd(&g_ocnt[g], 1);
                    g_idx[base + slot] = p;
                } else if (bin == bstar) {
                    int c = atomicAdd(&g_ccnt[g], 1);
                    if (c < 4096)
                        // value desc, then index asc (top_k tie rule)
                        g_cand[g][c] = ((unsigned long long)(u >> 9) << 16)
                                     | (unsigned long long)(0xFFFFu - (uint32_t)p);
                }
            }
        }
    }
}

// -------- selection stage 4: boundary-bin rank select (grid NG, 256 thr) ----
__global__ void __launch_bounds__(256) boundary_kernel() {
    int g = blockIdx.x, t = threadIdx.x;
    int b = g / 3, pick = g % 3;
    int base = b * K_ + ((pick == 0) ? 0 : (pick == 1) ? NFG : (NFG + NHARD));
    int c = g_ccnt[g]; if (c > 4096) c = 4096;
    int r = g_r[g];
    __shared__ unsigned long long cd[4096];
    for (int ci = t; ci < c; ci += 256) cd[ci] = g_cand[g][ci];
    __syncthreads();
    for (int ci = t; ci < c; ci += 256) {
        unsigned long long v = cd[ci];
        int rank = 0;
        for (int q = 0; q < c; ++q) rank += (cd[q] > v);
        if (rank < r) {
            int slot = atomicAdd(&g_ocnt[g], 1);
            g_idx[base + slot] = 0xFFFF - (int)(v & 0xFFFFull);
        }
    }
}

// -------- gather + L2-normalize + tf32 round (one warp per sample) --------
__global__ void gather_kernel(const float* __restrict__ feats,
                              const int* __restrict__ labels) {
    int gw   = (blockIdx.x * blockDim.x + threadIdx.x) >> 5;
    int lane = threadIdx.x & 31;
    if (gw >= B_ * K_) return;
    int b = gw / K_;
    int p = g_idx[gw];
    const float* f = feats + (size_t)b * C_ * P_ + p;
    float v0 = f[(size_t)lane * P_];
    float v1 = f[(size_t)(lane + 32) * P_];
    float ss = v0 * v0 + v1 * v1;
    #pragma unroll
    for (int o = 16; o; o >>= 1) ss += __shfl_xor_sync(0xFFFFFFFFu, ss, o);
    float inv = 1.0f / fmaxf(sqrtf(ss), 1e-12f);
    float* out = g_fsn + (size_t)gw * C_;
    out[lane]      = to_tf32(v0 * inv);   // tf32-matmul input semantics
    out[lane + 32] = to_tf32(v1 * inv);
    if (lane == 0) g_ys[gw] = labels[b * P_ + p];
}

// -------- fused Gram (tf32 mma) + softmax partials --------
// grid (jt=16, it=16, b=8), 256 thr = 8 warps (4 i-warps x 2 j-warps)
// Smem tiles XOR-swizzled: word addr = row*64 + ((c4 ^ (row&7))<<2) + w
__global__ void __launch_bounds__(256, 2) loss_mma_kernel() {
    extern __shared__ float smem[];
    float* xi = smem;            // 128 x 64
    float* xj = smem + 8192;     // 128 x 64
    __shared__ signed char ysi[128], ysj[128];
    __shared__ float rowd[128][2], rowp[128][2];

    int b  = blockIdx.z;
    int it = blockIdx.y;
    int jt = blockIdx.x;
    int t  = threadIdx.x;

    const float4* src_i = (const float4*)(g_fsn + ((size_t)b * K_ + it * 128) * C_);
    const float4* src_j = (const float4*)(g_fsn + ((size_t)b * K_ + jt * 128) * C_);
    for (int q = t; q < 2048; q += 256) {
        int row = q >> 4, c4 = q & 15;
        int dst = (row << 6) + ((c4 ^ (row & 7)) << 2);
        *(float4*)(xi + dst) = src_i[q];
        *(float4*)(xj + dst) = src_j[q];
    }
    if (t < 128) ysi[t] = (signed char)g_ys[b * K_ + it * 128 + t];
    else         ysj[t - 128] = (signed char)g_ys[b * K_ + jt * 128 + (t - 128)];
    __syncthreads();

    int w    = t >> 5;
    int lane = t & 31;
    int wi = w >> 1;             // 0..3 : i-strip of 32 rows
    int wj = w & 1;              // 0..1 : j-strip of 64 cols
    int g   = lane >> 2;         // groupID
    int tig = lane & 3;          // thread-in-group

    float c[2][8][4];
    #pragma unroll
    for (int m = 0; m < 2; ++m)
        #pragma unroll
        for (int n = 0; n < 8; ++n)
            { c[m][n][0]=0.f; c[m][n][1]=0.f; c[m][n][2]=0.f; c[m][n][3]=0.f; }

    #pragma unroll
    for (int ks = 0; ks < 8; ++ks) {
        int c4a = 2 * ks, c4b = 2 * ks + 1;
        float a[2][4];
        #pragma unroll
        for (int m = 0; m < 2; ++m) {
            int r0 = wi * 32 + m * 16 + g;
            int r1 = r0 + 8;
            int x0 = (r0 & 7);
            a[m][0] = xi[(r0 << 6) + ((c4a ^ x0) << 2) + tig];
            a[m][2] = xi[(r0 << 6) + ((c4b ^ x0) << 2) + tig];
            a[m][1] = xi[(r1 << 6) + ((c4a ^ x0) << 2) + tig];
            a[m][3] = xi[(r1 << 6) + ((c4b ^ x0) << 2) + tig];
        }
        float bf[8][2];
        #pragma unroll
        for (int n = 0; n < 8; ++n) {
            int jr = wj * 64 + n * 8 + g;
            int xo = (jr & 7);
            bf[n][0] = xj[(jr << 6) + ((c4a ^ xo) << 2) + tig];
            bf[n][1] = xj[(jr << 6) + ((c4b ^ xo) << 2) + tig];
        }
        #pragma unroll
        for (int m = 0; m < 2; ++m)
            #pragma unroll
            for (int n = 0; n < 8; ++n)
                mma_tf32(c[m][n], a[m], bf[n]);
    }

    // epilogue: exp + masked row sums (fixed order -> deterministic)
    signed char yj[16];
    #pragma unroll
    for (int n = 0; n < 8; ++n) {
        int col = wj * 64 + n * 8 + tig * 2;
        yj[2*n]   = ysj[col];
        yj[2*n+1] = ysj[col + 1];
    }
    bool diag = (it == jt);
    #pragma unroll
    for (int m = 0; m < 2; ++m) {
        int r0 = wi * 32 + m * 16 + g;
        int r1 = r0 + 8;
        int y0 = ysi[r0], y1 = ysi[r1];
        float d0 = 0.f, p0 = 0.f, d1 = 0.f, p1 = 0.f;
        #pragma unroll
        for (int n = 0; n < 8; ++n) {
            int col = wj * 64 + n * 8 + tig * 2;
            float e00 = ex2f(fmaf(c[m][n][0], C1_, C0_));
            float e01 = ex2f(fmaf(c[m][n][1], C1_, C0_));
            float e10 = ex2f(fmaf(c[m][n][2], C1_, C0_));
            float e11 = ex2f(fmaf(c[m][n][3], C1_, C0_));
            if (diag) {
                if (r0 == col)     e00 = 0.f;
                if (r0 == col + 1) e01 = 0.f;
                if (r1 == col)     e10 = 0.f;
                if (r1 == col + 1) e11 = 0.f;
            }
            d0 += e00 + e01;
            d1 += e10 + e11;
            p0 += ((y0 == yj[2*n]) ? e00 : 0.f) + ((y0 == yj[2*n+1]) ? e01 : 0.f);
            p1 += ((y1 == yj[2*n]) ? e10 : 0.f) + ((y1 == yj[2*n+1]) ? e11 : 0.f);
        }
        #pragma unroll
        for (int o = 1; o <= 2; o <<= 1) {
            d0 += __shfl_xor_sync(0xFFFFFFFFu, d0, o);
            p0 += __shfl_xor_sync(0xFFFFFFFFu, p0, o);
            d1 += __shfl_xor_sync(0xFFFFFFFFu, d1, o);
            p1 += __shfl_xor_sync(0xFFFFFFFFu, p1, o);
        }
        if (tig == 0) {
            rowd[r0][wj] = d0; rowp[r0][wj] = p0;
            rowd[r1][wj] = d1; rowp[r1][wj] = p1;
        }
    }
    __syncthreads();
    if (t < 128) {
        int gi = b * K_ + it * 128 + t;
        g_d [gi * NJT + jt] = rowd[t][0] + rowd[t][1];
        g_pp[gi * NJT + jt] = rowp[t][0] + rowp[t][1];
    }
}

// -------- per-row loss + per-image reduce (fixed summation order) --------
__global__ void __launch_bounds__(256) rowloss_kernel() {
    int b = blockIdx.x, t = threadIdx.x;
    float ls = 0.0f; int cnt = 0;
    for (int i = t; i < K_; i += 256) {
        int yi = g_ys[b * K_ + i];
        float dv = 0.0f, pv = 0.0f;
        #pragma unroll
        for (int js = 0; js < NJT; ++js) {
            dv += g_d [(b * K_ + i) * NJT + js];
            pv += g_pp[(b * K_ + i) * NJT + js];
        }
        if (yi == 1 && pv > 0.0f) {
            ls += logf(fmaxf(dv, 1e-8f)) - logf(fmaxf(pv, 1e-8f));
            cnt++;
        }
    }
    __shared__ float ss[256];
    __shared__ int   sc[256];
    ss[t] = ls; sc[t] = cnt;
    __syncthreads();
    for (int o = 128; o; o >>= 1) {
        if (t < o) { ss[t] += ss[t + o]; sc[t] += sc[t + o]; }
        __syncthreads();
    }
    if (t == 0) { g_loss_sum[b] = ss[0]; g_valid[b] = sc[0]; }
}

__global__ void final_kernel(float* out) {
    float s = 0.0f;
    for (int b = 0; b < B_; ++b) {
        int v = g_valid[b]; if (v < 1) v = 1;
        s += g_loss_sum[b] / (float)v;
    }
    out[0] = s / (float)B_;
}

// -------- launch --------
extern "C" void kernel_launch(void* const* d_in, const int* in_sizes, int n_in,
                              void* d_out, int out_size) {
    const float* feats  = (const float*)d_in[0];
    const int*   labels = (const int*)d_in[1];

    // Derive JAX keys host-side (deterministic; baked into graph as kernel args).
    KeyArg ka;
    uint32_t out16[16];
    for (int j = 0; j < 8; ++j)
        tf2x32(0u, 1u, (uint32_t)j, (uint32_t)(8 + j), out16[j], out16[8 + j]);
    for (int b = 0; b < B_; ++b) {
        uint32_t kb0 = out16[2 * b], kb1 = out16[2 * b + 1];
        uint32_t o6[6];
        for (int j = 0; j < 3; ++j)
            tf2x32(kb0, kb1, (uint32_t)j, (uint32_t)(3 + j), o6[j], o6[3 + j]);
        ka.k[b][0][0] = o6[0]; ka.k[b][0][1] = o6[1];   // k1 -> fg pick
        ka.k[b][1][0] = o6[2]; ka.k[b][1][1] = o6[3];   // k2 -> ring pick
        ka.k[b][2][0] = o6[4]; ka.k[b][2][1] = o6[5];   // k3 -> bg pick
    }

    // 64 KB dynamic smem opt-in (idempotent, not a stream op; graph-safe)
    static_assert(2 * 128 * 64 * sizeof(float) == 65536, "smem size");
    cudaFuncSetAttribute(loss_mma_kernel,
                         cudaFuncAttributeMaxDynamicSharedMemorySize, 65536);

    init_zero<<<(NZERO + 255) / 256, 256>>>();
    dim3 gmask(H_, B_);
    rowdil_kernel<<<gmask, W_>>>(labels);
    coldil_kernel<<<gmask, W_>>>();
    hash_hist_kernel<<<dim3(NG, 32), 256>>>(ka);
    scan_kernel<<<NG, 256>>>();
    emit_kernel<<<dim3(NG, 32), 256>>>();
    boundary_kernel<<<NG, 256>>>();
    gather_kernel<<<(B_ * K_ * 32 + 255) / 256, 256>>>(feats, labels);
    loss_mma_kernel<<<dim3(NJT, 16, B_), 256, 65536>>>();
    rowloss_kernel<<<B_, 256>>>();
    final_kernel<<<1, 1>>>((float*)d_out);
}

// round 7
// speedup vs baseline: 5.8504x; 1.1675x over previous
#include <cuda_runtime.h>
#include <cstdint>
#include <math.h>

#define B_ 8
#define C_ 64
#define H_ 256
#define W_ 256
#define P_ (H_*W_)
#define K_ 2048
#define NFG 1024
#define NHARD 768
#define NRAND 256
#define RADIUS_ 10
#define NG 24              // B_ * 3 picks
#define NJT 16             // j-tiles per row (2048/128)
#define NTILES (NJT*(NJT+1)/2)   // 136 upper-triangle tile pairs
// exp((c-1)/T) = 2^(c*C1 + C0),  C1 = log2(e)/T
#define C1_ 20.609929155555663f
#define C0_ (-20.609929155555663f)

// -------- scratch (static __device__, no allocations) --------
__device__ unsigned char g_rowdil[B_*P_];
__device__ unsigned char g_cat[B_*P_];          // bit0 = fg, bit1 = dilated
__device__ unsigned int g_hist[NG][2048];
__device__ int g_bstar[NG];
__device__ int g_r[NG];
__device__ unsigned long long g_cand[NG][4096];
__device__ int g_ccnt[NG];
__device__ int g_ocnt[NG];
__device__ int   g_idx[B_*K_];
__device__ int   g_ys [B_*K_];
__device__ float g_fsn[B_*K_*C_];               // tf32-rounded normalized feats
__device__ float g_d [B_*K_*NJT];               // deterministic partials
__device__ float g_pp[B_*K_*NJT];
__device__ float g_loss_sum[B_];
__device__ int   g_valid[B_];

// -------- small PTX helpers --------
__device__ __forceinline__ float ex2f(float x) {
    float y; asm("ex2.approx.f32 %0, %1;" : "=f"(y) : "f"(x)); return y;
}
__device__ __forceinline__ float to_tf32(float x) {
    uint32_t y; asm("cvt.rna.tf32.f32 %0, %1;" : "=r"(y) : "f"(x));
    return __uint_as_float(y);
}
__device__ __forceinline__ void mma_tf32(float c[4], const float a[4], const float b[2]) {
    asm volatile(
        "mma.sync.aligned.m16n8k8.row.col.f32.tf32.tf32.f32 "
        "{%0,%1,%2,%3}, {%4,%5,%6,%7}, {%8,%9}, {%0,%1,%2,%3};"
        : "+f"(c[0]), "+f"(c[1]), "+f"(c[2]), "+f"(c[3])
        : "r"(__float_as_uint(a[0])), "r"(__float_as_uint(a[1])),
          "r"(__float_as_uint(a[2])), "r"(__float_as_uint(a[3])),
          "r"(__float_as_uint(b[0])), "r"(__float_as_uint(b[1])));
}

// -------- Threefry-2x32 (matches JAX threefry2x32 exactly) --------
__host__ __device__ inline void tf2x32(uint32_t k0, uint32_t k1,
                                       uint32_t x0, uint32_t x1,
                                       uint32_t& o0, uint32_t& o1) {
    uint32_t ks2 = k0 ^ k1 ^ 0x1BD11BDAu;
    x0 += k0; x1 += k1;
#define RR(r) { x0 += x1; x1 = (x1 << r) | (x1 >> (32 - r)); x1 ^= x0; }
    RR(13) RR(15) RR(26) RR(6)  x0 += k1;  x1 += ks2 + 1u;
    RR(17) RR(29) RR(16) RR(24) x0 += ks2; x1 += k0  + 2u;
    RR(13) RR(15) RR(26) RR(6)  x0 += k0;  x1 += k1  + 3u;
    RR(17) RR(29) RR(16) RR(24) x0 += k1;  x1 += ks2 + 4u;
    RR(13) RR(15) RR(26) RR(6)  x0 += ks2; x1 += k0  + 5u;
#undef RR
    o0 = x0; o1 = x1;
}

__device__ __forceinline__ bool inmask(int pick, unsigned char c) {
    unsigned char m = c & 3;
    return (pick == 0) ? (m & 1) : (pick == 1) ? (m == 2) : (m == 0);
}

// -------- masks: separable 21x21 max-pool dilation (+ hist zeroing) --------
__global__ void rowdil_kernel(const int* __restrict__ labels) {
    int b = blockIdx.y, i = blockIdx.x, j = threadIdx.x;
    // piggyback: zero the selection histograms (runs before hash_hist in stream)
    int gtid = (blockIdx.y * gridDim.x + blockIdx.x) * W_ + j;
    if (gtid < NG * 2048) ((unsigned int*)g_hist)[gtid] = 0u;

    __shared__ unsigned char row[W_];
    int p = i * W_ + j;
    int fg = (labels[b * P_ + p] == 1);
    row[j] = (unsigned char)fg;
    __syncthreads();
    int lo = j - RADIUS_; if (lo < 0) lo = 0;
    int hi = j + RADIUS_; if (hi > W_ - 1) hi = W_ - 1;
    unsigned char od = 0;
    for (int jj = lo; jj <= hi; ++jj) od |= row[jj];
    g_rowdil[b * P_ + p] = od;
    g_cat[b * P_ + p] = (unsigned char)fg;
}

__global__ void coldil_kernel() {
    int b = blockIdx.y, i = blockIdx.x, j = threadIdx.x;
    int lo = i - RADIUS_; if (lo < 0) lo = 0;
    int hi = i + RADIUS_; if (hi > H_ - 1) hi = H_ - 1;
    unsigned char d = 0;
    for (int ii = lo; ii <= hi; ++ii) d |= g_rowdil[b * P_ + ii * W_ + j];
    int p = i * W_ + j;
    if (d) g_cat[b * P_ + p] |= 2;
}

// -------- selection stage 1: hash + histogram (grid NG x 32, 256 thr) -------
struct KeyArg { uint32_t k[B_][3][2]; };

__global__ void __launch_bounds__(256) hash_hist_kernel(KeyArg ka) {
    int g = blockIdx.x, chunk = blockIdx.y;
    int b = g / 3, pick = g % 3;
    uint32_t k0 = ka.k[b][pick][0], k1 = ka.k[b][pick][1];
    int t = threadIdx.x;
    __shared__ unsigned int h[2048];
    for (int q = t; q < 2048; q += 256) h[q] = 0u;
    __syncthreads();
    const unsigned char* cat = g_cat + b * P_;
    for (int kk = 0; kk < 4; ++kk) {
        int j = chunk * 1024 + kk * 256 + t;
        uint32_t o0, o1;
        tf2x32(k0, k1, (uint32_t)j, (uint32_t)(j + 32768), o0, o1);
        if (inmask(pick, cat[j]))         atomicAdd(&h[o0 >> 21], 1u);
        if (inmask(pick, cat[j + 32768])) atomicAdd(&h[o1 >> 21], 1u);
    }
    __syncthreads();
    for (int q = t; q < 2048; q += 256)
        if (h[q]) atomicAdd(&g_hist[g][q], h[q]);
}

// -------- selection stage 2: boundary bin (grid NG, 256 thr, zero counters) -
__global__ void __launch_bounds__(256) scan_kernel() {
    int g = blockIdx.x, t = threadIdx.x;
    int pick = g % 3;
    int n = (pick == 0) ? NFG : (pick == 1) ? NHARD : NRAND;
    if (t == 1) { g_ccnt[g] = 0; g_ocnt[g] = 0; }
    __shared__ unsigned int h[2048];
    __shared__ unsigned int part[256];
    for (int q = t; q < 2048; q += 256) h[q] = g_hist[g][q];
    __syncthreads();
    unsigned int s8 = 0;
    #pragma unroll
    for (int k = 0; k < 8; ++k) s8 += h[2047 - (t * 8 + k)];
    part[t] = s8;
    __syncthreads();
    if (t == 0) {
        int cum = 0, seg = 0;
        while (seg < 256 && cum + (int)part[seg] < n) { cum += (int)part[seg]; seg++; }
        int bstar = 0, above = cum;
        for (int k = 0; k < 8; ++k) {
            int q = 2047 - (seg * 8 + k);
            int hh = (int)h[q];
            if (cum + hh >= n) { bstar = q; above = cum; break; }
            cum += hh;
        }
        g_bstar[g] = bstar;
        g_r[g] = n - above;   // slots to fill from boundary bin
    }
}

// -------- selection stage 3: emit (grid NG x 32, 256 thr; recompute hash) ---
__global__ void __launch_bounds__(256) emit_kernel(KeyArg ka) {
    int g = blockIdx.x, chunk = blockIdx.y;
    int b = g / 3, pick = g % 3;
    int base = b * K_ + ((pick == 0) ? 0 : (pick == 1) ? NFG : (NFG + NHARD));
    uint32_t k0 = ka.k[b][pick][0], k1 = ka.k[b][pick][1];
    int bstar = g_bstar[g];
    int t = threadIdx.x;
    const unsigned char* cat = g_cat + b * P_;
    for (int kk = 0; kk < 4; ++kk) {
        int p0 = chunk * 1024 + kk * 256 + t;
        uint32_t o0, o1;
        tf2x32(k0, k1, (uint32_t)p0, (uint32_t)(p0 + 32768), o0, o1);
        #pragma unroll
        for (int hh = 0; hh < 2; ++hh) {
            int p = p0 + hh * 32768;
            uint32_t u = hh ? o1 : o0;
            if (inmask(pick, cat[p])) {
                int bin = (int)(u >> 21);
                if (bin > bstar) {
                    int slot = atomicAdd(&g_ocnt[g], 1);
                    g_idx[base + slot] = p;
                } else if (bin == bstar) {
                    int c = atomicAdd(&g_ccnt[g], 1);
                    if (c < 4096)
                        // value desc, then index asc (top_k tie rule)
                        g_cand[g][c] = ((unsigned long long)(u >> 9) << 16)
                                     | (unsigned long long)(0xFFFFu - (uint32_t)p);
                }
            }
        }
    }
}

// -------- selection stage 4: boundary-bin rank select (grid NG, 256 thr) ----
__global__ void __launch_bounds__(256) boundary_kernel() {
    int g = blockIdx.x, t = threadIdx.x;
    int b = g / 3, pick = g % 3;
    int base = b * K_ + ((pick == 0) ? 0 : (pick == 1) ? NFG : (NFG + NHARD));
    int c = g_ccnt[g]; if (c > 4096) c = 4096;
    int r = g_r[g];
    __shared__ unsigned long long cd[4096];
    for (int ci = t; ci < c; ci += 256) cd[ci] = g_cand[g][ci];
    __syncthreads();
    for (int ci = t; ci < c; ci += 256) {
        unsigned long long v = cd[ci];
        int rank = 0;
        for (int q = 0; q < c; ++q) rank += (cd[q] > v);
        if (rank < r) {
            int slot = atomicAdd(&g_ocnt[g], 1);
            g_idx[base + slot] = 0xFFFF - (int)(v & 0xFFFFull);
        }
    }
}

// -------- gather + L2-normalize + tf32 round (one warp per sample) --------
__global__ void gather_kernel(const float* __restrict__ feats,
                              const int* __restrict__ labels) {
    int gw   = (blockIdx.x * blockDim.x + threadIdx.x) >> 5;
    int lane = threadIdx.x & 31;
    if (gw >= B_ * K_) return;
    int b = gw / K_;
    int p = g_idx[gw];
    const float* f = feats + (size_t)b * C_ * P_ + p;
    float v0 = f[(size_t)lane * P_];
    float v1 = f[(size_t)(lane + 32) * P_];
    float ss = v0 * v0 + v1 * v1;
    #pragma unroll
    for (int o = 16; o; o >>= 1) ss += __shfl_xor_sync(0xFFFFFFFFu, ss, o);
    float inv = 1.0f / fmaxf(sqrtf(ss), 1e-12f);
    float* out = g_fsn + (size_t)gw * C_;
    out[lane]      = to_tf32(v0 * inv);   // tf32-matmul input semantics
    out[lane + 32] = to_tf32(v1 * inv);
    if (lane == 0) g_ys[gw] = labels[b * P_ + p];
}

// -------- fused Gram (tf32 mma, SYMMETRIC: upper-triangle tiles only) -------
// grid (136, b=8), 256 thr = 8 warps (4 i-warps x 2 j-warps)
// off-diagonal tiles produce BOTH row partials (slot jt) and col partials
// (slot it for j-rows). Every (row, slot) written by exactly one block.
__global__ void __launch_bounds__(256, 2) loss_mma_kernel() {
    extern __shared__ float smem[];
    float* xi = smem;            // 128 x 64
    float* xj = smem + 8192;     // 128 x 64
    __shared__ signed char ysi[128], ysj[128];
    __shared__ float rowd[128][2], rowp[128][2];
    __shared__ float cold[128][4], colp[128][4];

    int b = blockIdx.y;
    int u = blockIdx.x;
    int it = 0;
    while (u >= NJT - it) { u -= NJT - it; ++it; }
    int jt = it + u;
    bool diagT = (it == jt);
    int t = threadIdx.x;

    const float4* src_i = (const float4*)(g_fsn + ((size_t)b * K_ + it * 128) * C_);
    const float4* src_j = (const float4*)(g_fsn + ((size_t)b * K_ + jt * 128) * C_);
    for (int q = t; q < 2048; q += 256) {
        int row = q >> 4, c4 = q & 15;
        int dst = (row << 6) + ((c4 ^ (row & 7)) << 2);
        *(float4*)(xi + dst) = src_i[q];
        *(float4*)(xj + dst) = src_j[q];
    }
    if (t < 128) ysi[t] = (signed char)g_ys[b * K_ + it * 128 + t];
    else         ysj[t - 128] = (signed char)g_ys[b * K_ + jt * 128 + (t - 128)];
    __syncthreads();

    int w    = t >> 5;
    int lane = t & 31;
    int wi = w >> 1;             // 0..3 : i-strip of 32 rows
    int wj = w & 1;              // 0..1 : j-strip of 64 cols
    int g   = lane >> 2;         // groupID
    int tig = lane & 3;          // thread-in-group

    float c[2][8][4];
    #pragma unroll
    for (int m = 0; m < 2; ++m)
        #pragma unroll
        for (int n = 0; n < 8; ++n)
            { c[m][n][0]=0.f; c[m][n][1]=0.f; c[m][n][2]=0.f; c[m][n][3]=0.f; }

    #pragma unroll
    for (int ks = 0; ks < 8; ++ks) {
        int c4a = 2 * ks, c4b = 2 * ks + 1;
        float a[2][4];
        #pragma unroll
        for (int m = 0; m < 2; ++m) {
            int r0 = wi * 32 + m * 16 + g;
            int r1 = r0 + 8;
            int x0 = (r0 & 7);
            a[m][0] = xi[(r0 << 6) + ((c4a ^ x0) << 2) + tig];
            a[m][2] = xi[(r0 << 6) + ((c4b ^ x0) << 2) + tig];
            a[m][1] = xi[(r1 << 6) + ((c4a ^ x0) << 2) + tig];
            a[m][3] = xi[(r1 << 6) + ((c4b ^ x0) << 2) + tig];
        }
        float bf[8][2];
        #pragma unroll
        for (int n = 0; n < 8; ++n) {
            int jr = wj * 64 + n * 8 + g;
            int xo = (jr & 7);
            bf[n][0] = xj[(jr << 6) + ((c4a ^ xo) << 2) + tig];
            bf[n][1] = xj[(jr << 6) + ((c4b ^ xo) << 2) + tig];
        }
        #pragma unroll
        for (int m = 0; m < 2; ++m)
            #pragma unroll
            for (int n = 0; n < 8; ++n)
                mma_tf32(c[m][n], a[m], bf[n]);
    }

    // epilogue: exp + masked row sums + (off-diag) col sums, fixed order
    signed char yj[16];
    #pragma unroll
    for (int n = 0; n < 8; ++n) {
        int col = wj * 64 + n * 8 + tig * 2;
        yj[2*n]   = ysj[col];
        yj[2*n+1] = ysj[col + 1];
    }
    float cd0[8], cd1[8], cp0[8], cp1[8];
    #pragma unroll
    for (int n = 0; n < 8; ++n) { cd0[n]=0.f; cd1[n]=0.f; cp0[n]=0.f; cp1[n]=0.f; }

    #pragma unroll
    for (int m = 0; m < 2; ++m) {
        int r0 = wi * 32 + m * 16 + g;
        int r1 = r0 + 8;
        int y0 = ysi[r0], y1 = ysi[r1];
        float d0 = 0.f, p0 = 0.f, d1 = 0.f, p1 = 0.f;
        #pragma unroll
        for (int n = 0; n < 8; ++n) {
            int col = wj * 64 + n * 8 + tig * 2;
            float e00 = ex2f(fmaf(c[m][n][0], C1_, C0_));
            float e01 = ex2f(fmaf(c[m][n][1], C1_, C0_));
            float e10 = ex2f(fmaf(c[m][n][2], C1_, C0_));
            float e11 = ex2f(fmaf(c[m][n][3], C1_, C0_));
            if (diagT) {
                if (r0 == col)     e00 = 0.f;
                if (r0 == col + 1) e01 = 0.f;
                if (r1 == col)     e10 = 0.f;
                if (r1 == col + 1) e11 = 0.f;
            }
            bool q00 = (y0 == yj[2*n]), q01 = (y0 == yj[2*n+1]);
            bool q10 = (y1 == yj[2*n]), q11 = (y1 == yj[2*n+1]);
            d0 += e00 + e01;
            d1 += e10 + e11;
            p0 += (q00 ? e00 : 0.f) + (q01 ? e01 : 0.f);
            p1 += (q10 ? e10 : 0.f) + (q11 ? e11 : 0.f);
            if (!diagT) {
                cd0[n] += e00 + e10;
                cd1[n] += e01 + e11;
                cp0[n] += (q00 ? e00 : 0.f) + (q10 ? e10 : 0.f);
                cp1[n] += (q01 ? e01 : 0.f) + (q11 ? e11 : 0.f);
            }
        }
        #pragma unroll
        for (int o = 1; o <= 2; o <<= 1) {
            d0 += __shfl_xor_sync(0xFFFFFFFFu, d0, o);
            p0 += __shfl_xor_sync(0xFFFFFFFFu, p0, o);
            d1 += __shfl_xor_sync(0xFFFFFFFFu, d1, o);
            p1 += __shfl_xor_sync(0xFFFFFFFFu, p1, o);
        }
        if (tig == 0) {
            rowd[r0][wj] = d0; rowp[r0][wj] = p0;
            rowd[r1][wj] = d1; rowp[r1][wj] = p1;
        }
    }

    if (!diagT) {
        // reduce col sums over g (lane bits 2..4), then stash per-wi partials
        #pragma unroll
        for (int n = 0; n < 8; ++n) {
            #pragma unroll
            for (int o = 4; o <= 16; o <<= 1) {
                cd0[n] += __shfl_xor_sync(0xFFFFFFFFu, cd0[n], o);
                cd1[n] += __shfl_xor_sync(0xFFFFFFFFu, cd1[n], o);
                cp0[n] += __shfl_xor_sync(0xFFFFFFFFu, cp0[n], o);
                cp1[n] += __shfl_xor_sync(0xFFFFFFFFu, cp1[n], o);
            }
        }
        if (lane < 4) {          // g == 0, tig == lane
            #pragma unroll
            for (int n = 0; n < 8; ++n) {
                int col = wj * 64 + n * 8 + lane * 2;
                cold[col][wi]     = cd0[n]; colp[col][wi]     = cp0[n];
                cold[col + 1][wi] = cd1[n]; colp[col + 1][wi] = cp1[n];
            }
        }
    }
    __syncthreads();
    if (t < 128) {
        int gi = b * K_ + it * 128 + t;
        g_d [gi * NJT + jt] = rowd[t][0] + rowd[t][1];
        g_pp[gi * NJT + jt] = rowp[t][0] + rowp[t][1];
        if (!diagT) {
            int gj = b * K_ + jt * 128 + t;
            g_d [gj * NJT + it] = ((cold[t][0] + cold[t][1]) + (cold[t][2] + cold[t][3]));
            g_pp[gj * NJT + it] = ((colp[t][0] + colp[t][1]) + (colp[t][2] + colp[t][3]));
        }
    }
}

// -------- per-row loss + per-image reduce (fixed summation order) --------
__global__ void __launch_bounds__(256) rowloss_kernel() {
    int b = blockIdx.x, t = threadIdx.x;
    float ls = 0.0f; int cnt = 0;
    for (int i = t; i < K_; i += 256) {
        int yi = g_ys[b * K_ + i];
        float dv = 0.0f, pv = 0.0f;
        #pragma unroll
        for (int js = 0; js < NJT; ++js) {
            dv += g_d [(b * K_ + i) * NJT + js];
            pv += g_pp[(b * K_ + i) * NJT + js];
        }
        if (yi == 1 && pv > 0.0f) {
            ls += logf(fmaxf(dv, 1e-8f)) - logf(fmaxf(pv, 1e-8f));
            cnt++;
        }
    }
    __shared__ float ss[256];
    __shared__ int   sc[256];
    ss[t] = ls; sc[t] = cnt;
    __syncthreads();
    for (int o = 128; o; o >>= 1) {
        if (t < o) { ss[t] += ss[t + o]; sc[t] += sc[t + o]; }
        __syncthreads();
    }
    if (t == 0) { g_loss_sum[b] = ss[0]; g_valid[b] = sc[0]; }
}

__global__ void final_kernel(float* out) {
    float s = 0.0f;
    for (int b = 0; b < B_; ++b) {
        int v = g_valid[b]; if (v < 1) v = 1;
        s += g_loss_sum[b] / (float)v;
    }
    out[0] = s / (float)B_;
}

// -------- launch --------
extern "C" void kernel_launch(void* const* d_in, const int* in_sizes, int n_in,
                              void* d_out, int out_size) {
    const float* feats  = (const float*)d_in[0];
    const int*   labels = (const int*)d_in[1];

    // Derive JAX keys host-side (deterministic; baked into graph as kernel args).
    KeyArg ka;
    uint32_t out16[16];
    for (int j = 0; j < 8; ++j)
        tf2x32(0u, 1u, (uint32_t)j, (uint32_t)(8 + j), out16[j], out16[8 + j]);
    for (int b = 0; b < B_; ++b) {
        uint32_t kb0 = out16[2 * b], kb1 = out16[2 * b + 1];
        uint32_t o6[6];
        for (int j = 0; j < 3; ++j)
            tf2x32(kb0, kb1, (uint32_t)j, (uint32_t)(3 + j), o6[j], o6[3 + j]);
        ka.k[b][0][0] = o6[0]; ka.k[b][0][1] = o6[1];   // k1 -> fg pick
        ka.k[b][1][0] = o6[2]; ka.k[b][1][1] = o6[3];   // k2 -> ring pick
        ka.k[b][2][0] = o6[4]; ka.k[b][2][1] = o6[5];   // k3 -> bg pick
    }

    // 64 KB dynamic smem opt-in (idempotent; graph-safe)
    static_assert(2 * 128 * 64 * sizeof(float) == 65536, "smem size");
    cudaFuncSetAttribute(loss_mma_kernel,
                         cudaFuncAttributeMaxDynamicSharedMemorySize, 65536);

    dim3 gmask(H_, B_);
    rowdil_kernel<<<gmask, W_>>>(labels);
    coldil_kernel<<<gmask, W_>>>();
    hash_hist_kernel<<<dim3(NG, 32), 256>>>(ka);
    scan_kernel<<<NG, 256>>>();
    emit_kernel<<<dim3(NG, 32), 256>>>(ka);
    boundary_kernel<<<NG, 256>>>();
    gather_kernel<<<(B_ * K_ * 32 + 255) / 256, 256>>>(feats, labels);
    loss_mma_kernel<<<dim3(NTILES, B_), 256, 65536>>>();
    rowloss_kernel<<<B_, 256>>>();
    final_kernel<<<1, 1>>>((float*)d_out);
}

// round 8
// speedup vs baseline: 5.9938x; 1.0245x over previous
#include <cuda_runtime.h>
#include <cstdint>
#include <math.h>

#define B_ 8
#define C_ 64
#define H_ 256
#define W_ 256
#define P_ (H_*W_)
#define K_ 2048
#define NFG 1024
#define NHARD 768
#define NRAND 256
#define RADIUS_ 10
#define NG 24              // B_ * 3 picks
#define NJT 16             // j-tiles per row (2048/128)
#define NTILES (NJT*(NJT+1)/2)   // 136 upper-triangle tile pairs
// exp((c-1)/T) = 2^(c*C1 + C0),  C1 = log2(e)/T
#define C1_ 20.609929155555663f
#define C0_ (-20.609929155555663f)

// -------- scratch (static __device__, no allocations) --------
__device__ unsigned char g_rowdil[B_*P_];
__device__ unsigned char g_cat[B_*P_];          // bit0 = fg, bit1 = dilated
__device__ unsigned int g_hist[NG][2048];
__device__ int g_bstar[NG];
__device__ int g_r[NG];
__device__ unsigned long long g_cand[NG][4096];
__device__ int g_ccnt[NG];
__device__ int g_ocnt[NG];
__device__ unsigned int g_hdone[NG];            // last-block counters
__device__ unsigned int g_edone[NG];
__device__ unsigned int g_rldone;
__device__ int   g_idx[B_*K_];
__device__ int   g_ys [B_*K_];
__device__ float g_fsn[B_*K_*C_];               // tf32-rounded normalized feats
__device__ float g_d [B_*K_*NJT];               // deterministic partials
__device__ float g_pp[B_*K_*NJT];
__device__ float g_loss_sum[B_];
__device__ int   g_valid[B_];

// -------- small PTX helpers --------
__device__ __forceinline__ float ex2f(float x) {
    float y; asm("ex2.approx.f32 %0, %1;" : "=f"(y) : "f"(x)); return y;
}
__device__ __forceinline__ float to_tf32(float x) {
    uint32_t y; asm("cvt.rna.tf32.f32 %0, %1;" : "=r"(y) : "f"(x));
    return __uint_as_float(y);
}
__device__ __forceinline__ void mma_tf32(float c[4], const float a[4], const float b[2]) {
    asm volatile(
        "mma.sync.aligned.m16n8k8.row.col.f32.tf32.tf32.f32 "
        "{%0,%1,%2,%3}, {%4,%5,%6,%7}, {%8,%9}, {%0,%1,%2,%3};"
        : "+f"(c[0]), "+f"(c[1]), "+f"(c[2]), "+f"(c[3])
        : "r"(__float_as_uint(a[0])), "r"(__float_as_uint(a[1])),
          "r"(__float_as_uint(a[2])), "r"(__float_as_uint(a[3])),
          "r"(__float_as_uint(b[0])), "r"(__float_as_uint(b[1])));
}

// -------- Threefry-2x32 (matches JAX threefry2x32 exactly) --------
__host__ __device__ inline void tf2x32(uint32_t k0, uint32_t k1,
                                       uint32_t x0, uint32_t x1,
                                       uint32_t& o0, uint32_t& o1) {
    uint32_t ks2 = k0 ^ k1 ^ 0x1BD11BDAu;
    x0 += k0; x1 += k1;
#define RR(r) { x0 += x1; x1 = (x1 << r) | (x1 >> (32 - r)); x1 ^= x0; }
    RR(13) RR(15) RR(26) RR(6)  x0 += k1;  x1 += ks2 + 1u;
    RR(17) RR(29) RR(16) RR(24) x0 += ks2; x1 += k0  + 2u;
    RR(13) RR(15) RR(26) RR(6)  x0 += k0;  x1 += k1  + 3u;
    RR(17) RR(29) RR(16) RR(24) x0 += k1;  x1 += ks2 + 4u;
    RR(13) RR(15) RR(26) RR(6)  x0 += ks2; x1 += k0  + 5u;
#undef RR
    o0 = x0; o1 = x1;
}

__device__ __forceinline__ bool inmask(int pick, unsigned char c) {
    unsigned char m = c & 3;
    return (pick == 0) ? (m & 1) : (pick == 1) ? (m == 2) : (m == 0);
}

// -------- masks: separable 21x21 max-pool dilation (+ zero all counters) ----
__global__ void rowdil_kernel(const int* __restrict__ labels) {
    int b = blockIdx.y, i = blockIdx.x, j = threadIdx.x;
    // piggyback: zero hist + counters (stream-ordered before hash_hist)
    int gtid = (blockIdx.y * gridDim.x + blockIdx.x) * W_ + j;
    if (gtid < NG * 2048) ((unsigned int*)g_hist)[gtid] = 0u;
    else {
        int r = gtid - NG * 2048;
        if      (r < NG)      g_ccnt[r] = 0;
        else if (r < 2*NG)    g_ocnt[r - NG] = 0;
        else if (r < 3*NG)    g_hdone[r - 2*NG] = 0u;
        else if (r < 4*NG)    g_edone[r - 3*NG] = 0u;
        else if (r == 4*NG)   g_rldone = 0u;
    }

    __shared__ unsigned char row[W_];
    int p = i * W_ + j;
    int fg = (labels[b * P_ + p] == 1);
    row[j] = (unsigned char)fg;
    __syncthreads();
    int lo = j - RADIUS_; if (lo < 0) lo = 0;
    int hi = j + RADIUS_; if (hi > W_ - 1) hi = W_ - 1;
    unsigned char od = 0;
    for (int jj = lo; jj <= hi; ++jj) od |= row[jj];
    g_rowdil[b * P_ + p] = od;
    g_cat[b * P_ + p] = (unsigned char)fg;
}

__global__ void coldil_kernel() {
    int b = blockIdx.y, i = blockIdx.x, j = threadIdx.x;
    int lo = i - RADIUS_; if (lo < 0) lo = 0;
    int hi = i + RADIUS_; if (hi > H_ - 1) hi = H_ - 1;
    unsigned char d = 0;
    for (int ii = lo; ii <= hi; ++ii) d |= g_rowdil[b * P_ + ii * W_ + j];
    int p = i * W_ + j;
    if (d) g_cat[b * P_ + p] |= 2;
}

// -------- selection: hash + global histogram; last block per g does the scan
struct KeyArg { uint32_t k[B_][3][2]; };

__global__ void __launch_bounds__(256) hash_hist_kernel(KeyArg ka) {
    int g = blockIdx.x, chunk = blockIdx.y;
    int b = g / 3, pick = g % 3;
    uint32_t k0 = ka.k[b][pick][0], k1 = ka.k[b][pick][1];
    int t = threadIdx.x;
    const unsigned char* cat = g_cat + b * P_;
    for (int kk = 0; kk < 4; ++kk) {
        int j = chunk * 1024 + kk * 256 + t;
        uint32_t o0, o1;
        tf2x32(k0, k1, (uint32_t)j, (uint32_t)(j + 32768), o0, o1);
        if (inmask(pick, cat[j]))         atomicAdd(&g_hist[g][o0 >> 21], 1u);
        if (inmask(pick, cat[j + 32768])) atomicAdd(&g_hist[g][o1 >> 21], 1u);
    }
    __syncthreads();
    __shared__ int lastFlag;
    if (t == 0) {
        __threadfence();
        lastFlag = (atomicAdd(&g_hdone[g], 1u) == 31u);
    }
    __syncthreads();
    if (!lastFlag) return;

    // ---- fused scan: parallel prefix over 256 8-bin segments (desc order) --
    int n = (pick == 0) ? NFG : (pick == 1) ? NHARD : NRAND;
    unsigned int hv[8], s8 = 0;
    #pragma unroll
    for (int k = 0; k < 8; ++k) { hv[k] = g_hist[g][2047 - (t * 8 + k)]; s8 += hv[k]; }
    __shared__ unsigned int part[256];
    part[t] = s8;
    __syncthreads();
    #pragma unroll
    for (int off = 1; off < 256; off <<= 1) {
        unsigned int v = (t >= off) ? part[t - off] : 0u;
        __syncthreads();
        part[t] += v;
        __syncthreads();
    }
    int incl = (int)part[t];
    int before = incl - (int)s8;
    if (before < n && incl >= n) {          // exactly one owner thread
        int cum = before, bstar = 0, above = before;
        #pragma unroll
        for (int k = 0; k < 8; ++k) {
            int q = 2047 - (t * 8 + k);
            int hh = (int)hv[k];
            if (cum + hh >= n) { bstar = q; above = cum; break; }
            cum += hh;
        }
        g_bstar[g] = bstar;
        g_r[g] = n - above;
    }
}

// -------- emit (recompute hash); last block per g does boundary rank select -
__global__ void __launch_bounds__(256) emit_kernel(KeyArg ka) {
    int g = blockIdx.x, chunk = blockIdx.y;
    int b = g / 3, pick = g % 3;
    int base = b * K_ + ((pick == 0) ? 0 : (pick == 1) ? NFG : (NFG + NHARD));
    uint32_t k0 = ka.k[b][pick][0], k1 = ka.k[b][pick][1];
    int bstar = g_bstar[g];
    int t = threadIdx.x;
    const unsigned char* cat = g_cat + b * P_;
    for (int kk = 0; kk < 4; ++kk) {
        int p0 = chunk * 1024 + kk * 256 + t;
        uint32_t o0, o1;
        tf2x32(k0, k1, (uint32_t)p0, (uint32_t)(p0 + 32768), o0, o1);
        #pragma unroll
        for (int hh = 0; hh < 2; ++hh) {
            int p = p0 + hh * 32768;
            uint32_t u = hh ? o1 : o0;
            if (inmask(pick, cat[p])) {
                int bin = (int)(u >> 21);
                if (bin > bstar) {
                    int slot = atomicAdd(&g_ocnt[g], 1);
                    g_idx[base + slot] = p;
                } else if (bin == bstar) {
                    int c = atomicAdd(&g_ccnt[g], 1);
                    if (c < 4096)
                        // value desc, then index asc (top_k tie rule)
                        g_cand[g][c] = ((unsigned long long)(u >> 9) << 16)
                                     | (unsigned long long)(0xFFFFu - (uint32_t)p);
                }
            }
        }
    }
    __syncthreads();
    __shared__ int lastFlag;
    if (t == 0) {
        __threadfence();
        lastFlag = (atomicAdd(&g_edone[g], 1u) == 31u);
    }
    __syncthreads();
    if (!lastFlag) return;

    // ---- fused boundary-bin rank select ----
    int c = g_ccnt[g]; if (c > 4096) c = 4096;
    int r = g_r[g];
    __shared__ unsigned long long cd[4096];
    for (int ci = t; ci < c; ci += 256) cd[ci] = g_cand[g][ci];
    __syncthreads();
    for (int ci = t; ci < c; ci += 256) {
        unsigned long long v = cd[ci];
        int rank = 0;
        for (int q = 0; q < c; ++q) rank += (cd[q] > v);
        if (rank < r) {
            int slot = atomicAdd(&g_ocnt[g], 1);
            g_idx[base + slot] = 0xFFFF - (int)(v & 0xFFFFull);
        }
    }
}

// -------- gather + L2-normalize + tf32 round (one warp per sample) --------
__global__ void gather_kernel(const float* __restrict__ feats,
                              const int* __restrict__ labels) {
    int gw   = (blockIdx.x * blockDim.x + threadIdx.x) >> 5;
    int lane = threadIdx.x & 31;
    if (gw >= B_ * K_) return;
    int b = gw / K_;
    int p = g_idx[gw];
    const float* f = feats + (size_t)b * C_ * P_ + p;
    float v0 = f[(size_t)lane * P_];
    float v1 = f[(size_t)(lane + 32) * P_];
    float ss = v0 * v0 + v1 * v1;
    #pragma unroll
    for (int o = 16; o; o >>= 1) ss += __shfl_xor_sync(0xFFFFFFFFu, ss, o);
    float inv = 1.0f / fmaxf(sqrtf(ss), 1e-12f);
    float* out = g_fsn + (size_t)gw * C_;
    out[lane]      = to_tf32(v0 * inv);   // tf32-matmul input semantics
    out[lane + 32] = to_tf32(v1 * inv);
    if (lane == 0) g_ys[gw] = labels[b * P_ + p];
}

// -------- fused Gram (tf32 mma, SYMMETRIC: upper-triangle tiles only) -------
// grid (136, b=8), 256 thr = 8 warps (4 i-warps x 2 j-warps)
__global__ void __launch_bounds__(256, 2) loss_mma_kernel() {
    extern __shared__ float smem[];
    float* xi = smem;            // 128 x 64
    float* xj = smem + 8192;     // 128 x 64
    __shared__ signed char ysi[128], ysj[128];
    __shared__ float rowd[128][2], rowp[128][2];
    __shared__ float cold[128][4], colp[128][4];

    int b = blockIdx.y;
    int u = blockIdx.x;
    int it = 0;
    while (u >= NJT - it) { u -= NJT - it; ++it; }
    int jt = it + u;
    bool diagT = (it == jt);
    int t = threadIdx.x;

    const float4* src_i = (const float4*)(g_fsn + ((size_t)b * K_ + it * 128) * C_);
    const float4* src_j = (const float4*)(g_fsn + ((size_t)b * K_ + jt * 128) * C_);
    for (int q = t; q < 2048; q += 256) {
        int row = q >> 4, c4 = q & 15;
        int dst = (row << 6) + ((c4 ^ (row & 7)) << 2);
        *(float4*)(xi + dst) = src_i[q];
        *(float4*)(xj + dst) = src_j[q];
    }
    if (t < 128) ysi[t] = (signed char)g_ys[b * K_ + it * 128 + t];
    else         ysj[t - 128] = (signed char)g_ys[b * K_ + jt * 128 + (t - 128)];
    __syncthreads();

    int w    = t >> 5;
    int lane = t & 31;
    int wi = w >> 1;             // 0..3 : i-strip of 32 rows
    int wj = w & 1;              // 0..1 : j-strip of 64 cols
    int g   = lane >> 2;         // groupID
    int tig = lane & 3;          // thread-in-group

    float c[2][8][4];
    #pragma unroll
    for (int m = 0; m < 2; ++m)
        #pragma unroll
        for (int n = 0; n < 8; ++n)
            { c[m][n][0]=0.f; c[m][n][1]=0.f; c[m][n][2]=0.f; c[m][n][3]=0.f; }

    #pragma unroll
    for (int ks = 0; ks < 8; ++ks) {
        int c4a = 2 * ks, c4b = 2 * ks + 1;
        float a[2][4];
        #pragma unroll
        for (int m = 0; m < 2; ++m) {
            int r0 = wi * 32 + m * 16 + g;
            int r1 = r0 + 8;
            int x0 = (r0 & 7);
            a[m][0] = xi[(r0 << 6) + ((c4a ^ x0) << 2) + tig];
            a[m][2] = xi[(r0 << 6) + ((c4b ^ x0) << 2) + tig];
            a[m][1] = xi[(r1 << 6) + ((c4a ^ x0) << 2) + tig];
            a[m][3] = xi[(r1 << 6) + ((c4b ^ x0) << 2) + tig];
        }
        float bf[8][2];
        #pragma unroll
        for (int n = 0; n < 8; ++n) {
            int jr = wj * 64 + n * 8 + g;
            int xo = (jr & 7);
            bf[n][0] = xj[(jr << 6) + ((c4a ^ xo) << 2) + tig];
            bf[n][1] = xj[(jr << 6) + ((c4b ^ xo) << 2) + tig];
        }
        #pragma unroll
        for (int m = 0; m < 2; ++m)
            #pragma unroll
            for (int n = 0; n < 8; ++n)
                mma_tf32(c[m][n], a[m], bf[n]);
    }

    // epilogue: exp + masked row sums + (off-diag) col sums, fixed order
    signed char yj[16];
    #pragma unroll
    for (int n = 0; n < 8; ++n) {
        int col = wj * 64 + n * 8 + tig * 2;
        yj[2*n]   = ysj[col];
        yj[2*n+1] = ysj[col + 1];
    }
    float cd0[8], cd1[8], cp0[8], cp1[8];
    #pragma unroll
    for (int n = 0; n < 8; ++n) { cd0[n]=0.f; cd1[n]=0.f; cp0[n]=0.f; cp1[n]=0.f; }

    #pragma unroll
    for (int m = 0; m < 2; ++m) {
        int r0 = wi * 32 + m * 16 + g;
        int r1 = r0 + 8;
        int y0 = ysi[r0], y1 = ysi[r1];
        float d0 = 0.f, p0 = 0.f, d1 = 0.f, p1 = 0.f;
        #pragma unroll
        for (int n = 0; n < 8; ++n) {
            int col = wj * 64 + n * 8 + tig * 2;
            float e00 = ex2f(fmaf(c[m][n][0], C1_, C0_));
            float e01 = ex2f(fmaf(c[m][n][1], C1_, C0_));
            float e10 = ex2f(fmaf(c[m][n][2], C1_, C0_));
            float e11 = ex2f(fmaf(c[m][n][3], C1_, C0_));
            if (diagT) {
                if (r0 == col)     e00 = 0.f;
                if (r0 == col + 1) e01 = 0.f;
                if (r1 == col)     e10 = 0.f;
                if (r1 == col + 1) e11 = 0.f;
            }
            bool q00 = (y0 == yj[2*n]), q01 = (y0 == yj[2*n+1]);
            bool q10 = (y1 == yj[2*n]), q11 = (y1 == yj[2*n+1]);
            d0 += e00 + e01;
            d1 += e10 + e11;
            p0 += (q00 ? e00 : 0.f) + (q01 ? e01 : 0.f);
            p1 += (q10 ? e10 : 0.f) + (q11 ? e11 : 0.f);
            if (!diagT) {
                cd0[n] += e00 + e10;
                cd1[n] += e01 + e11;
                cp0[n] += (q00 ? e00 : 0.f) + (q10 ? e10 : 0.f);
                cp1[n] += (q01 ? e01 : 0.f) + (q11 ? e11 : 0.f);
            }
        }
        #pragma unroll
        for (int o = 1; o <= 2; o <<= 1) {
            d0 += __shfl_xor_sync(0xFFFFFFFFu, d0, o);
            p0 += __shfl_xor_sync(0xFFFFFFFFu, p0, o);
            d1 += __shfl_xor_sync(0xFFFFFFFFu, d1, o);
            p1 += __shfl_xor_sync(0xFFFFFFFFu, p1, o);
        }
        if (tig == 0) {
            rowd[r0][wj] = d0; rowp[r0][wj] = p0;
            rowd[r1][wj] = d1; rowp[r1][wj] = p1;
        }
    }

    if (!diagT) {
        #pragma unroll
        for (int n = 0; n < 8; ++n) {
            #pragma unroll
            for (int o = 4; o <= 16; o <<= 1) {
                cd0[n] += __shfl_xor_sync(0xFFFFFFFFu, cd0[n], o);
                cd1[n] += __shfl_xor_sync(0xFFFFFFFFu, cd1[n], o);
                cp0[n] += __shfl_xor_sync(0xFFFFFFFFu, cp0[n], o);
                cp1[n] += __shfl_xor_sync(0xFFFFFFFFu, cp1[n], o);
            }
        }
        if (lane < 4) {          // g == 0, tig == lane
            #pragma unroll
            for (int n = 0; n < 8; ++n) {
                int col = wj * 64 + n * 8 + lane * 2;
                cold[col][wi]     = cd0[n]; colp[col][wi]     = cp0[n];
                cold[col + 1][wi] = cd1[n]; colp[col + 1][wi] = cp1[n];
            }
        }
    }
    __syncthreads();
    if (t < 128) {
        int gi = b * K_ + it * 128 + t;
        g_d [gi * NJT + jt] = rowd[t][0] + rowd[t][1];
        g_pp[gi * NJT + jt] = rowp[t][0] + rowp[t][1];
        if (!diagT) {
            int gj = b * K_ + jt * 128 + t;
            g_d [gj * NJT + it] = ((cold[t][0] + cold[t][1]) + (cold[t][2] + cold[t][3]));
            g_pp[gj * NJT + it] = ((colp[t][0] + colp[t][1]) + (colp[t][2] + colp[t][3]));
        }
    }
}

// -------- per-row loss + per-image reduce; last block writes final scalar ---
__global__ void __launch_bounds__(256) rowloss_kernel(float* out) {
    int b = blockIdx.x, t = threadIdx.x;
    float ls = 0.0f; int cnt = 0;
    for (int i = t; i < K_; i += 256) {
        int yi = g_ys[b * K_ + i];
        float dv = 0.0f, pv = 0.0f;
        #pragma unroll
        for (int js = 0; js < NJT; ++js) {
            dv += g_d [(b * K_ + i) * NJT + js];
            pv += g_pp[(b * K_ + i) * NJT + js];
        }
        if (yi == 1 && pv > 0.0f) {
            ls += logf(fmaxf(dv, 1e-8f)) - logf(fmaxf(pv, 1e-8f));
            cnt++;
        }
    }
    __shared__ float ss[256];
    __shared__ int   sc[256];
    ss[t] = ls; sc[t] = cnt;
    __syncthreads();
    for (int o = 128; o; o >>= 1) {
        if (t < o) { ss[t] += ss[t + o]; sc[t] += sc[t + o]; }
        __syncthreads();
    }
    if (t == 0) { g_loss_sum[b] = ss[0]; g_valid[b] = sc[0]; }
    __syncthreads();
    __shared__ int lastFlag;
    if (t == 0) {
        __threadfence();
        lastFlag = (atomicAdd(&g_rldone, 1u) == (unsigned)(B_ - 1));
    }
    __syncthreads();
    if (lastFlag && t == 0) {
        float s = 0.0f;
        for (int bb = 0; bb < B_; ++bb) {        // fixed order -> deterministic
            int v = g_valid[bb]; if (v < 1) v = 1;
            s += g_loss_sum[bb] / (float)v;
        }
        out[0] = s / (float)B_;
    }
}

// -------- launch --------
extern "C" void kernel_launch(void* const* d_in, const int* in_sizes, int n_in,
                              void* d_out, int out_size) {
    const float* feats  = (const float*)d_in[0];
    const int*   labels = (const int*)d_in[1];

    // Derive JAX keys host-side (deterministic; baked into graph as kernel args).
    KeyArg ka;
    uint32_t out16[16];
    for (int j = 0; j < 8; ++j)
        tf2x32(0u, 1u, (uint32_t)j, (uint32_t)(8 + j), out16[j], out16[8 + j]);
    for (int b = 0; b < B_; ++b) {
        uint32_t kb0 = out16[2 * b], kb1 = out16[2 * b + 1];
        uint32_t o6[6];
        for (int j = 0; j < 3; ++j)
            tf2x32(kb0, kb1, (uint32_t)j, (uint32_t)(3 + j), o6[j], o6[3 + j]);
        ka.k[b][0][0] = o6[0]; ka.k[b][0][1] = o6[1];   // k1 -> fg pick
        ka.k[b][1][0] = o6[2]; ka.k[b][1][1] = o6[3];   // k2 -> ring pick
        ka.k[b][2][0] = o6[4]; ka.k[b][2][1] = o6[5];   // k3 -> bg pick
    }

    // 64 KB dynamic smem opt-in (idempotent; graph-safe)
    static_assert(2 * 128 * 64 * sizeof(float) == 65536, "smem size");
    cudaFuncSetAttribute(loss_mma_kernel,
                         cudaFuncAttributeMaxDynamicSharedMemorySize, 65536);

    dim3 gmask(H_, B_);
    rowdil_kernel<<<gmask, W_>>>(labels);
    coldil_kernel<<<gmask, W_>>>();
    hash_hist_kernel<<<dim3(NG, 32), 256>>>(ka);
    emit_kernel<<<dim3(NG, 32), 256>>>(ka);
    gather_kernel<<<(B_ * K_ * 32 + 255) / 256, 256>>>(feats, labels);
    loss_mma_kernel<<<dim3(NTILES, B_), 256, 65536>>>();
    rowloss_kernel<<<B_, 256>>>((float*)d_out);
}